// round 11
// baseline (speedup 1.0000x reference)
#include <cuda_runtime.h>
#include <cuda_bf16.h>
#include <cuda_fp16.h>
#include <math.h>
#include <stdint.h>

#define B_ 8
#define C_ 512
#define L_ 1024
#define NH_ 8
#define DH_ 64
#define NG_ 32

// scratch (no cudaMalloc allowed)
__device__ __half g_xnh[B_ * C_ * L_];            // [b][c][l]  8 MB
__device__ __half g_qkvh[B_ * 3 * C_ * L_];       // [b][m][l] 24 MB
__device__ __half g_attnh[B_ * C_ * L_];          // [b][c][l]  8 MB
__device__ __half g_wqkvh[3 * C_ * C_];           // [m][c]
__device__ __half g_wprojh[C_ * C_];              // [m][c]

// ---------------------------------------------------------------------------
// asm helpers
// ---------------------------------------------------------------------------
__device__ __forceinline__ void cp16(void* dst_smem, const void* src) {
    unsigned d = (unsigned)__cvta_generic_to_shared(dst_smem);
    asm volatile("cp.async.cg.shared.global [%0], [%1], 16;\n" :: "r"(d), "l"(src));
}
__device__ __forceinline__ void cp_commit() {
    asm volatile("cp.async.commit_group;\n");
}
template <int N> __device__ __forceinline__ void cp_wait() {
    asm volatile("cp.async.wait_group %0;\n" :: "n"(N));
}
__device__ __forceinline__ void ldsm4(unsigned* r, const void* p) {
    unsigned a = (unsigned)__cvta_generic_to_shared(p);
    asm volatile("ldmatrix.sync.aligned.m8n8.x4.shared.b16 {%0,%1,%2,%3}, [%4];\n"
                 : "=r"(r[0]), "=r"(r[1]), "=r"(r[2]), "=r"(r[3]) : "r"(a));
}
__device__ __forceinline__ void ldsm4t(unsigned* r, const void* p) {
    unsigned a = (unsigned)__cvta_generic_to_shared(p);
    asm volatile("ldmatrix.sync.aligned.m8n8.x4.trans.shared.b16 {%0,%1,%2,%3}, [%4];\n"
                 : "=r"(r[0]), "=r"(r[1]), "=r"(r[2]), "=r"(r[3]) : "r"(a));
}
__device__ __forceinline__ void mma16816(float* d, const unsigned* a,
                                         const unsigned* b, const float* c) {
    asm volatile(
        "mma.sync.aligned.m16n8k16.row.col.f32.f16.f16.f32 "
        "{%0,%1,%2,%3}, {%4,%5,%6,%7}, {%8,%9}, {%10,%11,%12,%13};\n"
        : "=f"(d[0]), "=f"(d[1]), "=f"(d[2]), "=f"(d[3])
        : "r"(a[0]), "r"(a[1]), "r"(a[2]), "r"(a[3]), "r"(b[0]), "r"(b[1]),
          "f"(c[0]), "f"(c[1]), "f"(c[2]), "f"(c[3]));
}
__device__ __forceinline__ unsigned packh2(float a, float b) {
    __half2 h = __floats2half2_rn(a, b);
    return *(unsigned*)&h;
}
__device__ __forceinline__ unsigned ex2h2(unsigned x) {
    unsigned r;
    asm("ex2.approx.f16x2 %0, %1;" : "=r"(r) : "r"(x));
    return r;
}

// ---------------------------------------------------------------------------
// GroupNorm(32) + weight conversion fused in one launch.
// Blocks [0,256): GN per (b, group). Blocks [256,320): weight fp32->fp16.
// ---------------------------------------------------------------------------
__global__ void gn_kernel(const float* __restrict__ x,
                          const float* __restrict__ gs,
                          const float* __restrict__ gb,
                          const float* __restrict__ qkv_w,
                          const float* __restrict__ proj_w) {
    if (blockIdx.x >= 256) {
        // weight conversion: 64 blocks x 4096 float4 = 1048576 floats total
        int blk = blockIdx.x - 256;
        #pragma unroll
        for (int u = 0; u < 16; u++) {
            int i4 = blk * 4096 + threadIdx.x + u * 256;
            int i = i4 * 4;
            float4 v;
            __half2* dst;
            if (i < 3 * C_ * C_) {
                v = *(const float4*)&qkv_w[i];
                dst = (__half2*)&g_wqkvh[i];
            } else {
                v = *(const float4*)&proj_w[i - 3 * C_ * C_];
                dst = (__half2*)&g_wprojh[i - 3 * C_ * C_];
            }
            dst[0] = __floats2half2_rn(v.x, v.y);
            dst[1] = __floats2half2_rn(v.z, v.w);
        }
        return;
    }

    int b = blockIdx.x >> 5;
    int g = blockIdx.x & 31;
    const float* xp = x + ((size_t)b * C_ + (size_t)g * 16) * L_;
    __half* op = g_xnh + ((size_t)b * C_ + (size_t)g * 16) * L_;

    float sum = 0.f, sq = 0.f;
    for (int i = threadIdx.x; i < 4096; i += blockDim.x) {
        float4 v = ((const float4*)xp)[i];
        sum += v.x + v.y + v.z + v.w;
        sq  += v.x * v.x + v.y * v.y + v.z * v.z + v.w * v.w;
    }
    __shared__ float ssum[32], ssq[32];
    int lane = threadIdx.x & 31, wid = threadIdx.x >> 5;
    #pragma unroll
    for (int m = 16; m > 0; m >>= 1) {
        sum += __shfl_xor_sync(0xffffffffu, sum, m);
        sq  += __shfl_xor_sync(0xffffffffu, sq,  m);
    }
    if (lane == 0) { ssum[wid] = sum; ssq[wid] = sq; }
    __syncthreads();
    int nw = blockDim.x >> 5;
    if (wid == 0) {
        float s = (lane < nw) ? ssum[lane] : 0.f;
        float q = (lane < nw) ? ssq[lane] : 0.f;
        #pragma unroll
        for (int m = 16; m > 0; m >>= 1) {
            s += __shfl_xor_sync(0xffffffffu, s, m);
            q += __shfl_xor_sync(0xffffffffu, q, m);
        }
        if (lane == 0) { ssum[0] = s; ssq[0] = q; }
    }
    __syncthreads();
    float mu = ssum[0] * (1.f / 16384.f);
    float var = ssq[0] * (1.f / 16384.f) - mu * mu;
    float inv = rsqrtf(var + 1e-5f);

    for (int i = threadIdx.x; i < 4096; i += blockDim.x) {
        int ch = g * 16 + (i >> 8);
        float sc = gs[ch] * inv;
        float bs = gb[ch] - mu * sc;
        float4 v = ((const float4*)xp)[i];
        __half2 h0 = __floats2half2_rn(v.x * sc + bs, v.y * sc + bs);
        __half2 h1 = __floats2half2_rn(v.z * sc + bs, v.w * sc + bs);
        ((__half2*)op)[2 * i]     = h0;
        ((__half2*)op)[2 * i + 1] = h1;
    }
}

// ---------------------------------------------------------------------------
// Raw-mma fp16 GEMM (unchanged, passing).
// ---------------------------------------------------------------------------
__global__ __launch_bounds__(256) void gemm_mma_kernel(
        const __half* __restrict__ Wh, const float* __restrict__ bias,
        const __half* __restrict__ X, const float* __restrict__ res,
        void* __restrict__ Y, int M, int mode) {
    __shared__ __align__(16) __half As[2][128][40];
    __shared__ __align__(16) __half Bs[2][32][136];

    int tid = threadIdx.x;
    int wid = tid >> 5;
    int lane = tid & 31;
    int wm = wid & 3;
    int wn = wid >> 2;
    int bz = blockIdx.z;
    int m0 = blockIdx.y * 128;
    int n0 = blockIdx.x * 128;
    const __half* Xb = X + (size_t)bz * C_ * L_;

    float acc[2][8][4];
    #pragma unroll
    for (int mt = 0; mt < 2; mt++)
        #pragma unroll
        for (int nt = 0; nt < 8; nt++)
            #pragma unroll
            for (int e = 0; e < 4; e++) acc[mt][nt][e] = 0.f;

    int a_r0 = tid >> 2,          a_c0 = (tid & 3) << 3;
    int a_r1 = (tid + 256) >> 2,  a_c1 = ((tid + 256) & 3) << 3;
    int b_r0 = tid >> 4,          b_c0 = (tid & 15) << 3;
    int b_r1 = (tid + 256) >> 4,  b_c1 = ((tid + 256) & 15) << 3;

    cp16(&As[0][a_r0][a_c0], &Wh[(size_t)(m0 + a_r0) * C_ + a_c0]);
    cp16(&As[0][a_r1][a_c1], &Wh[(size_t)(m0 + a_r1) * C_ + a_c1]);
    cp16(&Bs[0][b_r0][b_c0], &Xb[(size_t)b_r0 * L_ + n0 + b_c0]);
    cp16(&Bs[0][b_r1][b_c1], &Xb[(size_t)b_r1 * L_ + n0 + b_c1]);
    cp_commit();

    int arow = wm * 32 + (lane & 7) + ((lane >> 3) & 1) * 8;
    int acol = ((lane >> 4) & 1) * 8;
    int brow = (lane & 7) + ((lane >> 3) & 1) * 8;
    int bcol = wn * 64 + ((lane >> 4) & 1) * 8;

    const int NIT = C_ / 32;     // 16
    int s = 0;
    for (int it = 0; it < NIT; it++) {
        if (it + 1 < NIT) {
            int k0 = (it + 1) * 32;
            cp16(&As[s ^ 1][a_r0][a_c0], &Wh[(size_t)(m0 + a_r0) * C_ + k0 + a_c0]);
            cp16(&As[s ^ 1][a_r1][a_c1], &Wh[(size_t)(m0 + a_r1) * C_ + k0 + a_c1]);
            cp16(&Bs[s ^ 1][b_r0][b_c0], &Xb[(size_t)(k0 + b_r0) * L_ + n0 + b_c0]);
            cp16(&Bs[s ^ 1][b_r1][b_c1], &Xb[(size_t)(k0 + b_r1) * L_ + n0 + b_c1]);
            cp_commit();
            cp_wait<1>();
        } else {
            cp_wait<0>();
        }
        __syncthreads();

        #pragma unroll
        for (int kk = 0; kk < 32; kk += 16) {
            unsigned af[2][4];
            ldsm4(af[0], &As[s][arow][kk + acol]);
            ldsm4(af[1], &As[s][arow + 16][kk + acol]);
            #pragma unroll
            for (int g = 0; g < 4; g++) {
                unsigned bf[4];
                ldsm4t(bf, &Bs[s][kk + brow][bcol + g * 16]);
                mma16816(acc[0][2 * g],     af[0], bf,     acc[0][2 * g]);
                mma16816(acc[0][2 * g + 1], af[0], bf + 2, acc[0][2 * g + 1]);
                mma16816(acc[1][2 * g],     af[1], bf,     acc[1][2 * g]);
                mma16816(acc[1][2 * g + 1], af[1], bf + 2, acc[1][2 * g + 1]);
            }
        }
        __syncthreads();
        s ^= 1;
    }

    int rbase = m0 + wm * 32 + (lane >> 2);
    int cbase = n0 + wn * 64 + (lane & 3) * 2;

    if (mode == 0) {
        __half* Yh = (__half*)Y + (size_t)bz * M * L_;
        #pragma unroll
        for (int mt = 0; mt < 2; mt++) {
            int r = rbase + mt * 16;
            float bs0 = bias[r], bs1 = bias[r + 8];
            float sc0 = (r < 512)     ? 0.18033688011112043f : 1.f;
            float sc1 = (r + 8 < 512) ? 0.18033688011112043f : 1.f;
            #pragma unroll
            for (int nt = 0; nt < 8; nt++) {
                int c = cbase + nt * 8;
                float* a = acc[mt][nt];
                *(__half2*)&Yh[(size_t)r * L_ + c] =
                    __floats2half2_rn((a[0] + bs0) * sc0, (a[1] + bs0) * sc0);
                *(__half2*)&Yh[(size_t)(r + 8) * L_ + c] =
                    __floats2half2_rn((a[2] + bs1) * sc1, (a[3] + bs1) * sc1);
            }
        }
    } else {
        float* Yf = (float*)Y + (size_t)bz * M * L_;
        const float* Rb = res + (size_t)bz * M * L_;
        #pragma unroll
        for (int mt = 0; mt < 2; mt++) {
            int r = rbase + mt * 16;
            float bs0 = bias[r], bs1 = bias[r + 8];
            #pragma unroll
            for (int nt = 0; nt < 8; nt++) {
                int c = cbase + nt * 8;
                float* a = acc[mt][nt];
                float2 r0 = *(const float2*)&Rb[(size_t)r * L_ + c];
                float2 r1 = *(const float2*)&Rb[(size_t)(r + 8) * L_ + c];
                float2 o0 = make_float2(a[0] + bs0 + r0.x, a[1] + bs0 + r0.y);
                float2 o1 = make_float2(a[2] + bs1 + r1.x, a[3] + bs1 + r1.y);
                *(float2*)&Yf[(size_t)r * L_ + c] = o0;
                *(float2*)&Yf[(size_t)(r + 8) * L_ + c] = o1;
            }
        }
    }
}

// ---------------------------------------------------------------------------
// Flash attention, warp m-tile 32 (t-tile 256/block):
//  - each kb/vb ldsm feeds 4 mma (ldsm:mma 0.375 vs 1.0 before)
//  - S computed/consumed in two 32-wide s half-passes (register control)
//  - 3-stage cp.async ring, 1 barrier/iter; fp16x2 exp
// smem: Qh[256][72] (36864) | Kh[3][64][72] | Vh[3][64][72]  = 92160 B
// ---------------------------------------------------------------------------
__global__ __launch_bounds__(256, 2) void attn_kernel() {
    extern __shared__ __align__(16) unsigned char dsm[];
    __half (*Qh)[72]     = (__half (*)[72])dsm;                  // 36864 B
    __half (*Kh)[64][72] = (__half (*)[64][72])(dsm + 36864);    // 27648 B
    __half (*Vh)[64][72] = (__half (*)[64][72])(dsm + 64512);    // 27648 B
    __half (*Pc)[264]    = (__half (*)[264])(dsm + 36864);       // alias 33792 B

    int bh = blockIdx.y;
    int b = bh >> 3, h = bh & 7;
    int t0 = blockIdx.x * 256;

    const __half* Qg = g_qkvh + ((size_t)b * 3 * C_ + (size_t)h * DH_) * L_;
    const __half* Kg = Qg + (size_t)C_ * L_;
    const __half* Vg = Qg + (size_t)2 * C_ * L_;

    int tid = threadIdx.x;
    int lane = tid & 31;
    int w = tid >> 5;

    int kr0 = tid >> 3, kc0 = (tid & 7) << 3;
    int kr1 = (tid + 256) >> 3, kc1 = ((tid + 256) & 7) << 3;

    // prologue: stages 0 and 1
    cp16(&Kh[0][kr0][kc0], &Kg[(size_t)kr0 * L_ + kc0]);
    cp16(&Kh[0][kr1][kc1], &Kg[(size_t)kr1 * L_ + kc1]);
    cp16(&Vh[0][kr0][kc0], &Vg[(size_t)kr0 * L_ + kc0]);
    cp16(&Vh[0][kr1][kc1], &Vg[(size_t)kr1 * L_ + kc1]);
    cp_commit();
    cp16(&Kh[1][kr0][kc0], &Kg[(size_t)kr0 * L_ + 64 + kc0]);
    cp16(&Kh[1][kr1][kc1], &Kg[(size_t)kr1 * L_ + 64 + kc1]);
    cp16(&Vh[1][kr0][kc0], &Vg[(size_t)kr0 * L_ + 64 + kc0]);
    cp16(&Vh[1][kr1][kc1], &Vg[(size_t)kr1 * L_ + 64 + kc1]);
    cp_commit();

    // Q -> smem [t][c]  (16384 halfs)
    #pragma unroll
    for (int u = 0; u < 64; u++) {
        int idx = tid + u * 256;
        int c = idx >> 8, t = idx & 255;
        Qh[t][c] = Qg[(size_t)c * L_ + t0 + t];
    }
    __syncthreads();

    float oacc[2][8][4];
    #pragma unroll
    for (int mt = 0; mt < 2; mt++)
        #pragma unroll
        for (int nt = 0; nt < 8; nt++)
            #pragma unroll
            for (int e = 0; e < 4; e++) oacc[mt][nt][e] = 0.f;
    float lsum[2][2] = {{0.f, 0.f}, {0.f, 0.f}};

    int q_row = 32 * w + (lane & 7) + ((lane >> 3) & 1) * 8;   // mt0; mt1: +16
    int q_col = ((lane >> 4) & 1) * 8;
    int kq_row = ((lane >> 3) & 1) * 8 + (lane & 7);
    int kq_col = ((lane >> 4) & 1) * 8;
    int vq_row = ((lane >> 4) & 1) * 8 + (lane & 7);
    int vq_col = ((lane >> 3) & 1) * 8;

    for (int it = 0; it < 16; it++) {
        int s = it % 3;
        if (it < 15) cp_wait<1>(); else cp_wait<0>();
        __syncthreads();
        if (it < 14) {
            int st = (it + 2) % 3;
            int s0 = (it + 2) * 64;
            cp16(&Kh[st][kr0][kc0], &Kg[(size_t)kr0 * L_ + s0 + kc0]);
            cp16(&Kh[st][kr1][kc1], &Kg[(size_t)kr1 * L_ + s0 + kc1]);
            cp16(&Vh[st][kr0][kc0], &Vg[(size_t)kr0 * L_ + s0 + kc0]);
            cp16(&Vh[st][kr1][kc1], &Vg[(size_t)kr1 * L_ + s0 + kc1]);
            cp_commit();
        }

        // two s half-passes: S(32 wide) -> exp -> PV, registers stay bounded
        #pragma unroll
        for (int hp = 0; hp < 2; hp++) {
            float sacc[2][4][4];
            #pragma unroll
            for (int mt = 0; mt < 2; mt++)
                #pragma unroll
                for (int nt = 0; nt < 4; nt++)
                    #pragma unroll
                    for (int e = 0; e < 4; e++) sacc[mt][nt][e] = 0.f;

            #pragma unroll
            for (int kk = 0; kk < 4; kk++) {
                unsigned qa0[4], qa1[4];
                ldsm4(qa0, &Qh[q_row][kk * 16 + q_col]);
                ldsm4(qa1, &Qh[q_row + 16][kk * 16 + q_col]);
                #pragma unroll
                for (int st2 = 0; st2 < 2; st2++) {
                    int st = hp * 2 + st2;
                    unsigned kb[4];
                    ldsm4t(kb, &Kh[s][kk * 16 + kq_row][st * 16 + kq_col]);
                    mma16816(sacc[0][2 * st2],     qa0, kb,     sacc[0][2 * st2]);
                    mma16816(sacc[0][2 * st2 + 1], qa0, kb + 2, sacc[0][2 * st2 + 1]);
                    mma16816(sacc[1][2 * st2],     qa1, kb,     sacc[1][2 * st2]);
                    mma16816(sacc[1][2 * st2 + 1], qa1, kb + 2, sacc[1][2 * st2 + 1]);
                }
            }

            // P = exp2(S) fp16x2, row sums
            unsigned pa[2][4][2];
            #pragma unroll
            for (int mt = 0; mt < 2; mt++) {
                __half2 th0 = __float2half2_rn(0.f), th1 = __float2half2_rn(0.f);
                #pragma unroll
                for (int nt = 0; nt < 4; nt++) {
                    pa[mt][nt][0] = ex2h2(packh2(sacc[mt][nt][0], sacc[mt][nt][1]));
                    pa[mt][nt][1] = ex2h2(packh2(sacc[mt][nt][2], sacc[mt][nt][3]));
                    th0 = __hadd2(th0, *(__half2*)&pa[mt][nt][0]);
                    th1 = __hadd2(th1, *(__half2*)&pa[mt][nt][1]);
                }
                float2 f0 = __half22float2(th0);
                float2 f1 = __half22float2(th1);
                lsum[mt][0] += f0.x + f0.y;
                lsum[mt][1] += f1.x + f1.y;
            }

            // O += P V^T over this hp's 32 s-values
            #pragma unroll
            for (int kc2 = 0; kc2 < 2; kc2++) {
                int kcg = hp * 2 + kc2;
                unsigned af0[4] = {pa[0][2 * kc2][0], pa[0][2 * kc2][1],
                                   pa[0][2 * kc2 + 1][0], pa[0][2 * kc2 + 1][1]};
                unsigned af1[4] = {pa[1][2 * kc2][0], pa[1][2 * kc2][1],
                                   pa[1][2 * kc2 + 1][0], pa[1][2 * kc2 + 1][1]};
                #pragma unroll
                for (int ct = 0; ct < 4; ct++) {
                    unsigned vb[4];
                    ldsm4(vb, &Vh[s][ct * 16 + vq_row][kcg * 16 + vq_col]);
                    mma16816(oacc[0][2 * ct],     af0, vb,     oacc[0][2 * ct]);
                    mma16816(oacc[0][2 * ct + 1], af0, vb + 2, oacc[0][2 * ct + 1]);
                    mma16816(oacc[1][2 * ct],     af1, vb,     oacc[1][2 * ct]);
                    mma16816(oacc[1][2 * ct + 1], af1, vb + 2, oacc[1][2 * ct + 1]);
                }
            }
        }
    }
    __syncthreads();   // all K/V reads done before Pc alias writes

    #pragma unroll
    for (int mt = 0; mt < 2; mt++) {
        lsum[mt][0] += __shfl_xor_sync(0xffffffffu, lsum[mt][0], 1);
        lsum[mt][0] += __shfl_xor_sync(0xffffffffu, lsum[mt][0], 2);
        lsum[mt][1] += __shfl_xor_sync(0xffffffffu, lsum[mt][1], 1);
        lsum[mt][1] += __shfl_xor_sync(0xffffffffu, lsum[mt][1], 2);
    }

    int g = lane >> 2, q = lane & 3;
    #pragma unroll
    for (int mt = 0; mt < 2; mt++) {
        int trow = 32 * w + 16 * mt + g;
        float inv0 = 1.f / lsum[mt][0];
        float inv1 = 1.f / lsum[mt][1];
        #pragma unroll
        for (int nt = 0; nt < 8; nt++) {
            int c = nt * 8 + 2 * q;
            float* a = oacc[mt][nt];
            __half2 lo = __floats2half2_rn(a[0] * inv0, a[1] * inv0);
            __half2 hi = __floats2half2_rn(a[2] * inv1, a[3] * inv1);
            Pc[c][trow]         = __low2half(lo);
            Pc[c + 1][trow]     = __high2half(lo);
            Pc[c][trow + 8]     = __low2half(hi);
            Pc[c + 1][trow + 8] = __high2half(hi);
        }
    }
    __syncthreads();

    // coalesced write: 64 c-rows x 256 t = 2048 uint4
    #pragma unroll
    for (int u = 0; u < 8; u++) {
        int idx = tid + u * 256;
        int c = idx >> 5, pos = idx & 31;
        uint4 v = *(uint4*)&Pc[c][pos * 8];
        *(uint4*)&g_attnh[((size_t)b * C_ + h * DH_ + c) * L_ + t0 + pos * 8] = v;
    }
}

// ---------------------------------------------------------------------------
extern "C" void kernel_launch(void* const* d_in, const int* in_sizes, int n_in,
                              void* d_out, int out_size) {
    const float* x      = (const float*)d_in[0];
    const float* gs     = (const float*)d_in[1];
    const float* gb     = (const float*)d_in[2];
    const float* qkv_w  = (const float*)d_in[3];
    const float* qkv_b  = (const float*)d_in[4];
    const float* proj_w = (const float*)d_in[5];
    const float* proj_b = (const float*)d_in[6];
    float* out = (float*)d_out;

    __half *xnh, *qkvh, *attnh, *wqkvh, *wprojh;
    cudaGetSymbolAddress((void**)&xnh,    g_xnh);
    cudaGetSymbolAddress((void**)&qkvh,   g_qkvh);
    cudaGetSymbolAddress((void**)&attnh,  g_attnh);
    cudaGetSymbolAddress((void**)&wqkvh,  g_wqkvh);
    cudaGetSymbolAddress((void**)&wprojh, g_wprojh);

    cudaFuncSetAttribute(attn_kernel, cudaFuncAttributeMaxDynamicSharedMemorySize,
                         92160);

    // 1. GroupNorm -> fp16 [b][c][l]  (+ fused weight conversion blocks)
    gn_kernel<<<B_ * NG_ + 64, 256>>>(x, gs, gb, qkv_w, proj_w);

    // 2. qkv GEMM: M=1536, K=512 (q rows scaled by log2e/8 in epilogue)
    {
        dim3 grid(L_ / 128, (3 * C_) / 128, B_);
        gemm_mma_kernel<<<grid, 256>>>(wqkvh, qkv_b, xnh, nullptr, qkvh,
                                       3 * C_, 0);
    }

    // 3. flash attention, warp m-tile 32 (t-tile 256)
    {
        dim3 grid(L_ / 256, B_ * NH_);
        attn_kernel<<<grid, 256, 92160>>>();
    }

    // 4. proj GEMM + bias + residual -> fp32 out
    {
        dim3 grid(L_ / 128, C_ / 128, B_);
        gemm_mma_kernel<<<grid, 256>>>(wprojh, proj_b, attnh, x, out,
                                       C_, 1);
    }
}

// round 12
// speedup vs baseline: 1.1158x; 1.1158x over previous
#include <cuda_runtime.h>
#include <cuda_bf16.h>
#include <cuda_fp16.h>
#include <math.h>
#include <stdint.h>

#define B_ 8
#define C_ 512
#define L_ 1024
#define NH_ 8
#define DH_ 64
#define NG_ 32

// scratch (no cudaMalloc allowed)
__device__ __half g_xnh[B_ * C_ * L_];            // [b][c][l]  8 MB
__device__ __half g_qkvh[B_ * 3 * C_ * L_];       // [b][m][l] 24 MB
__device__ __half g_attnh[B_ * C_ * L_];          // [b][c][l]  8 MB
__device__ __half g_wqkvh[3 * C_ * C_];           // [m][c]
__device__ __half g_wprojh[C_ * C_];              // [m][c]

// ---------------------------------------------------------------------------
// asm helpers
// ---------------------------------------------------------------------------
__device__ __forceinline__ void cp16(void* dst_smem, const void* src) {
    unsigned d = (unsigned)__cvta_generic_to_shared(dst_smem);
    asm volatile("cp.async.cg.shared.global [%0], [%1], 16;\n" :: "r"(d), "l"(src));
}
__device__ __forceinline__ void cp_commit() {
    asm volatile("cp.async.commit_group;\n");
}
template <int N> __device__ __forceinline__ void cp_wait() {
    asm volatile("cp.async.wait_group %0;\n" :: "n"(N));
}
__device__ __forceinline__ void ldsm4(unsigned* r, const void* p) {
    unsigned a = (unsigned)__cvta_generic_to_shared(p);
    asm volatile("ldmatrix.sync.aligned.m8n8.x4.shared.b16 {%0,%1,%2,%3}, [%4];\n"
                 : "=r"(r[0]), "=r"(r[1]), "=r"(r[2]), "=r"(r[3]) : "r"(a));
}
__device__ __forceinline__ void ldsm4t(unsigned* r, const void* p) {
    unsigned a = (unsigned)__cvta_generic_to_shared(p);
    asm volatile("ldmatrix.sync.aligned.m8n8.x4.trans.shared.b16 {%0,%1,%2,%3}, [%4];\n"
                 : "=r"(r[0]), "=r"(r[1]), "=r"(r[2]), "=r"(r[3]) : "r"(a));
}
__device__ __forceinline__ void mma16816(float* d, const unsigned* a,
                                         const unsigned* b, const float* c) {
    asm volatile(
        "mma.sync.aligned.m16n8k16.row.col.f32.f16.f16.f32 "
        "{%0,%1,%2,%3}, {%4,%5,%6,%7}, {%8,%9}, {%10,%11,%12,%13};\n"
        : "=f"(d[0]), "=f"(d[1]), "=f"(d[2]), "=f"(d[3])
        : "r"(a[0]), "r"(a[1]), "r"(a[2]), "r"(a[3]), "r"(b[0]), "r"(b[1]),
          "f"(c[0]), "f"(c[1]), "f"(c[2]), "f"(c[3]));
}
__device__ __forceinline__ unsigned packh2(float a, float b) {
    __half2 h = __floats2half2_rn(a, b);
    return *(unsigned*)&h;
}
__device__ __forceinline__ unsigned ex2h2(unsigned x) {
    unsigned r;
    asm("ex2.approx.f16x2 %0, %1;" : "=r"(r) : "r"(x));
    return r;
}

// ---------------------------------------------------------------------------
// GroupNorm(32) + weight conversion fused in one launch.
// Blocks [0,256): GN per (b, group). Blocks [256,320): weight fp32->fp16.
// ---------------------------------------------------------------------------
__global__ void gn_kernel(const float* __restrict__ x,
                          const float* __restrict__ gs,
                          const float* __restrict__ gb,
                          const float* __restrict__ qkv_w,
                          const float* __restrict__ proj_w) {
    if (blockIdx.x >= 256) {
        int blk = blockIdx.x - 256;
        #pragma unroll
        for (int u = 0; u < 16; u++) {
            int i4 = blk * 4096 + threadIdx.x + u * 256;
            int i = i4 * 4;
            float4 v;
            __half2* dst;
            if (i < 3 * C_ * C_) {
                v = *(const float4*)&qkv_w[i];
                dst = (__half2*)&g_wqkvh[i];
            } else {
                v = *(const float4*)&proj_w[i - 3 * C_ * C_];
                dst = (__half2*)&g_wprojh[i - 3 * C_ * C_];
            }
            dst[0] = __floats2half2_rn(v.x, v.y);
            dst[1] = __floats2half2_rn(v.z, v.w);
        }
        return;
    }

    int b = blockIdx.x >> 5;
    int g = blockIdx.x & 31;
    const float* xp = x + ((size_t)b * C_ + (size_t)g * 16) * L_;
    __half* op = g_xnh + ((size_t)b * C_ + (size_t)g * 16) * L_;

    float sum = 0.f, sq = 0.f;
    for (int i = threadIdx.x; i < 4096; i += blockDim.x) {
        float4 v = ((const float4*)xp)[i];
        sum += v.x + v.y + v.z + v.w;
        sq  += v.x * v.x + v.y * v.y + v.z * v.z + v.w * v.w;
    }
    __shared__ float ssum[32], ssq[32];
    int lane = threadIdx.x & 31, wid = threadIdx.x >> 5;
    #pragma unroll
    for (int m = 16; m > 0; m >>= 1) {
        sum += __shfl_xor_sync(0xffffffffu, sum, m);
        sq  += __shfl_xor_sync(0xffffffffu, sq,  m);
    }
    if (lane == 0) { ssum[wid] = sum; ssq[wid] = sq; }
    __syncthreads();
    int nw = blockDim.x >> 5;
    if (wid == 0) {
        float s = (lane < nw) ? ssum[lane] : 0.f;
        float q = (lane < nw) ? ssq[lane] : 0.f;
        #pragma unroll
        for (int m = 16; m > 0; m >>= 1) {
            s += __shfl_xor_sync(0xffffffffu, s, m);
            q += __shfl_xor_sync(0xffffffffu, q, m);
        }
        if (lane == 0) { ssum[0] = s; ssq[0] = q; }
    }
    __syncthreads();
    float mu = ssum[0] * (1.f / 16384.f);
    float var = ssq[0] * (1.f / 16384.f) - mu * mu;
    float inv = rsqrtf(var + 1e-5f);

    for (int i = threadIdx.x; i < 4096; i += blockDim.x) {
        int ch = g * 16 + (i >> 8);
        float sc = gs[ch] * inv;
        float bs = gb[ch] - mu * sc;
        float4 v = ((const float4*)xp)[i];
        __half2 h0 = __floats2half2_rn(v.x * sc + bs, v.y * sc + bs);
        __half2 h1 = __floats2half2_rn(v.z * sc + bs, v.w * sc + bs);
        ((__half2*)op)[2 * i]     = h0;
        ((__half2*)op)[2 * i + 1] = h1;
    }
}

// ---------------------------------------------------------------------------
// Raw-mma fp16 GEMM, 3-stage cp.async ring, ONE barrier per K-iteration.
// Block 128m x 128n, 8 warps (4m x 2n), BK=32.
// dyn smem: As 3x128x40 + Bs 3x32x136 halfs = 56832 B
// ---------------------------------------------------------------------------
__global__ __launch_bounds__(256) void gemm_mma_kernel(
        const __half* __restrict__ Wh, const float* __restrict__ bias,
        const __half* __restrict__ X, const float* __restrict__ res,
        void* __restrict__ Y, int M, int mode) {
    extern __shared__ __align__(16) unsigned char gsm[];
    __half (*As)[128][40] = (__half (*)[128][40])gsm;            // 30720 B
    __half (*Bs)[32][136] = (__half (*)[32][136])(gsm + 30720);  // 26112 B

    int tid = threadIdx.x;
    int wid = tid >> 5;
    int lane = tid & 31;
    int wm = wid & 3;
    int wn = wid >> 2;
    int bz = blockIdx.z;
    int m0 = blockIdx.y * 128;
    int n0 = blockIdx.x * 128;
    const __half* Xb = X + (size_t)bz * C_ * L_;

    float acc[2][8][4];
    #pragma unroll
    for (int mt = 0; mt < 2; mt++)
        #pragma unroll
        for (int nt = 0; nt < 8; nt++)
            #pragma unroll
            for (int e = 0; e < 4; e++) acc[mt][nt][e] = 0.f;

    int a_r0 = tid >> 2,          a_c0 = (tid & 3) << 3;
    int a_r1 = (tid + 256) >> 2,  a_c1 = ((tid + 256) & 3) << 3;
    int b_r0 = tid >> 4,          b_c0 = (tid & 15) << 3;
    int b_r1 = (tid + 256) >> 4,  b_c1 = ((tid + 256) & 15) << 3;

    // prologue: stages 0 and 1
    #pragma unroll
    for (int p = 0; p < 2; p++) {
        int k0 = p * 32;
        cp16(&As[p][a_r0][a_c0], &Wh[(size_t)(m0 + a_r0) * C_ + k0 + a_c0]);
        cp16(&As[p][a_r1][a_c1], &Wh[(size_t)(m0 + a_r1) * C_ + k0 + a_c1]);
        cp16(&Bs[p][b_r0][b_c0], &Xb[(size_t)(k0 + b_r0) * L_ + n0 + b_c0]);
        cp16(&Bs[p][b_r1][b_c1], &Xb[(size_t)(k0 + b_r1) * L_ + n0 + b_c1]);
        cp_commit();
    }

    int arow = wm * 32 + (lane & 7) + ((lane >> 3) & 1) * 8;
    int acol = ((lane >> 4) & 1) * 8;
    int brow = (lane & 7) + ((lane >> 3) & 1) * 8;
    int bcol = wn * 64 + ((lane >> 4) & 1) * 8;

    const int NIT = C_ / 32;     // 16
    for (int it = 0; it < NIT; it++) {
        int s = it % 3;
        if (it + 1 < NIT) cp_wait<1>(); else cp_wait<0>();
        __syncthreads();
        if (it + 2 < NIT) {
            int st = (it + 2) % 3;
            int k0 = (it + 2) * 32;
            cp16(&As[st][a_r0][a_c0], &Wh[(size_t)(m0 + a_r0) * C_ + k0 + a_c0]);
            cp16(&As[st][a_r1][a_c1], &Wh[(size_t)(m0 + a_r1) * C_ + k0 + a_c1]);
            cp16(&Bs[st][b_r0][b_c0], &Xb[(size_t)(k0 + b_r0) * L_ + n0 + b_c0]);
            cp16(&Bs[st][b_r1][b_c1], &Xb[(size_t)(k0 + b_r1) * L_ + n0 + b_c1]);
            cp_commit();
        }

        #pragma unroll
        for (int kk = 0; kk < 32; kk += 16) {
            unsigned af[2][4];
            ldsm4(af[0], &As[s][arow][kk + acol]);
            ldsm4(af[1], &As[s][arow + 16][kk + acol]);
            #pragma unroll
            for (int g = 0; g < 4; g++) {
                unsigned bf[4];
                ldsm4t(bf, &Bs[s][kk + brow][bcol + g * 16]);
                mma16816(acc[0][2 * g],     af[0], bf,     acc[0][2 * g]);
                mma16816(acc[0][2 * g + 1], af[0], bf + 2, acc[0][2 * g + 1]);
                mma16816(acc[1][2 * g],     af[1], bf,     acc[1][2 * g]);
                mma16816(acc[1][2 * g + 1], af[1], bf + 2, acc[1][2 * g + 1]);
            }
        }
        // no trailing barrier: next iteration's barrier protects stage reuse
    }

    int rbase = m0 + wm * 32 + (lane >> 2);
    int cbase = n0 + wn * 64 + (lane & 3) * 2;

    if (mode == 0) {
        __half* Yh = (__half*)Y + (size_t)bz * M * L_;
        #pragma unroll
        for (int mt = 0; mt < 2; mt++) {
            int r = rbase + mt * 16;
            float bs0 = bias[r], bs1 = bias[r + 8];
            float sc0 = (r < 512)     ? 0.18033688011112043f : 1.f;
            float sc1 = (r + 8 < 512) ? 0.18033688011112043f : 1.f;
            #pragma unroll
            for (int nt = 0; nt < 8; nt++) {
                int c = cbase + nt * 8;
                float* a = acc[mt][nt];
                *(__half2*)&Yh[(size_t)r * L_ + c] =
                    __floats2half2_rn((a[0] + bs0) * sc0, (a[1] + bs0) * sc0);
                *(__half2*)&Yh[(size_t)(r + 8) * L_ + c] =
                    __floats2half2_rn((a[2] + bs1) * sc1, (a[3] + bs1) * sc1);
            }
        }
    } else {
        float* Yf = (float*)Y + (size_t)bz * M * L_;
        const float* Rb = res + (size_t)bz * M * L_;
        #pragma unroll
        for (int mt = 0; mt < 2; mt++) {
            int r = rbase + mt * 16;
            float bs0 = bias[r], bs1 = bias[r + 8];
            #pragma unroll
            for (int nt = 0; nt < 8; nt++) {
                int c = cbase + nt * 8;
                float* a = acc[mt][nt];
                float2 r0 = *(const float2*)&Rb[(size_t)r * L_ + c];
                float2 r1 = *(const float2*)&Rb[(size_t)(r + 8) * L_ + c];
                float2 o0 = make_float2(a[0] + bs0 + r0.x, a[1] + bs0 + r0.y);
                float2 o1 = make_float2(a[2] + bs1 + r1.x, a[3] + bs1 + r1.y);
                *(float2*)&Yf[(size_t)r * L_ + c] = o0;
                *(float2*)&Yf[(size_t)(r + 8) * L_ + c] = o1;
            }
        }
    }
}

// ---------------------------------------------------------------------------
// Register-resident flash attention — exact R10 version (best measured).
// smem: Qh[128][72] | Kh[3][64][72] | Vh[3][64][72]   (73728 B dynamic)
// ---------------------------------------------------------------------------
__global__ __launch_bounds__(256) void attn_kernel() {
    extern __shared__ __align__(16) unsigned char dsm[];
    __half (*Qh)[72]     = (__half (*)[72])dsm;                  // 18432 B
    __half (*Kh)[64][72] = (__half (*)[64][72])(dsm + 18432);    // 27648 B
    __half (*Vh)[64][72] = (__half (*)[64][72])(dsm + 46080);    // 27648 B
    __half (*Pc)[136]    = (__half (*)[136])(dsm + 18432);       // alias (17408 B)

    int bh = blockIdx.y;
    int b = bh >> 3, h = bh & 7;
    int t0 = blockIdx.x * 128;

    const __half* Qg = g_qkvh + ((size_t)b * 3 * C_ + (size_t)h * DH_) * L_;
    const __half* Kg = Qg + (size_t)C_ * L_;
    const __half* Vg = Qg + (size_t)2 * C_ * L_;

    int tid = threadIdx.x;
    int lane = tid & 31;
    int w = tid >> 5;

    int kr0 = tid >> 3, kc0 = (tid & 7) << 3;
    int kr1 = (tid + 256) >> 3, kc1 = ((tid + 256) & 7) << 3;

    cp16(&Kh[0][kr0][kc0], &Kg[(size_t)kr0 * L_ + kc0]);
    cp16(&Kh[0][kr1][kc1], &Kg[(size_t)kr1 * L_ + kc1]);
    cp16(&Vh[0][kr0][kc0], &Vg[(size_t)kr0 * L_ + kc0]);
    cp16(&Vh[0][kr1][kc1], &Vg[(size_t)kr1 * L_ + kc1]);
    cp_commit();
    cp16(&Kh[1][kr0][kc0], &Kg[(size_t)kr0 * L_ + 64 + kc0]);
    cp16(&Kh[1][kr1][kc1], &Kg[(size_t)kr1 * L_ + 64 + kc1]);
    cp16(&Vh[1][kr0][kc0], &Vg[(size_t)kr0 * L_ + 64 + kc0]);
    cp16(&Vh[1][kr1][kc1], &Vg[(size_t)kr1 * L_ + 64 + kc1]);
    cp_commit();

    #pragma unroll
    for (int u = 0; u < 32; u++) {
        int idx = tid + u * 256;
        int c = idx >> 7, t = idx & 127;
        Qh[t][c] = Qg[(size_t)c * L_ + t0 + t];
    }
    __syncthreads();

    unsigned qa[4][4];
    {
        int m = 16 * w + (lane & 7) + ((lane >> 3) & 1) * 8;
        int cb = ((lane >> 4) & 1) * 8;
        #pragma unroll
        for (int kk = 0; kk < 4; kk++)
            ldsm4(qa[kk], &Qh[m][kk * 16 + cb]);
    }

    float oacc[8][4];
    #pragma unroll
    for (int nt = 0; nt < 8; nt++)
        #pragma unroll
        for (int e = 0; e < 4; e++) oacc[nt][e] = 0.f;
    float lsum0 = 0.f, lsum1 = 0.f;

    int kq_row = ((lane >> 3) & 1) * 8 + (lane & 7);
    int kq_col = ((lane >> 4) & 1) * 8;
    int vq_row = ((lane >> 4) & 1) * 8 + (lane & 7);
    int vq_col = ((lane >> 3) & 1) * 8;

    for (int it = 0; it < 16; it++) {
        int s = it % 3;
        if (it < 15) cp_wait<1>(); else cp_wait<0>();
        __syncthreads();
        if (it < 14) {
            int st = (it + 2) % 3;
            int s0 = (it + 2) * 64;
            cp16(&Kh[st][kr0][kc0], &Kg[(size_t)kr0 * L_ + s0 + kc0]);
            cp16(&Kh[st][kr1][kc1], &Kg[(size_t)kr1 * L_ + s0 + kc1]);
            cp16(&Vh[st][kr0][kc0], &Vg[(size_t)kr0 * L_ + s0 + kc0]);
            cp16(&Vh[st][kr1][kc1], &Vg[(size_t)kr1 * L_ + s0 + kc1]);
            cp_commit();
        }

        float sacc[8][4];
        #pragma unroll
        for (int nt = 0; nt < 8; nt++)
            #pragma unroll
            for (int e = 0; e < 4; e++) sacc[nt][e] = 0.f;

        #pragma unroll
        for (int kk = 0; kk < 4; kk++) {
            #pragma unroll
            for (int st = 0; st < 4; st++) {
                unsigned kb[4];
                ldsm4t(kb, &Kh[s][kk * 16 + kq_row][st * 16 + kq_col]);
                mma16816(sacc[2 * st],     qa[kk], kb,     sacc[2 * st]);
                mma16816(sacc[2 * st + 1], qa[kk], kb + 2, sacc[2 * st + 1]);
            }
        }

        unsigned pa[8][2];
        __half2 t0h = __float2half2_rn(0.f), t1h = __float2half2_rn(0.f);
        #pragma unroll
        for (int nt = 0; nt < 8; nt++) {
            pa[nt][0] = ex2h2(packh2(sacc[nt][0], sacc[nt][1]));
            pa[nt][1] = ex2h2(packh2(sacc[nt][2], sacc[nt][3]));
            t0h = __hadd2(t0h, *(__half2*)&pa[nt][0]);
            t1h = __hadd2(t1h, *(__half2*)&pa[nt][1]);
        }
        {
            float2 f0 = __half22float2(t0h);
            float2 f1 = __half22float2(t1h);
            lsum0 += f0.x + f0.y;
            lsum1 += f1.x + f1.y;
        }

        #pragma unroll
        for (int kc = 0; kc < 4; kc++) {
            unsigned af[4] = {pa[2 * kc][0], pa[2 * kc][1],
                              pa[2 * kc + 1][0], pa[2 * kc + 1][1]};
            #pragma unroll
            for (int ct = 0; ct < 4; ct++) {
                unsigned vb[4];
                ldsm4(vb, &Vh[s][ct * 16 + vq_row][kc * 16 + vq_col]);
                mma16816(oacc[2 * ct],     af, vb,     oacc[2 * ct]);
                mma16816(oacc[2 * ct + 1], af, vb + 2, oacc[2 * ct + 1]);
            }
        }
    }
    __syncthreads();

    lsum0 += __shfl_xor_sync(0xffffffffu, lsum0, 1);
    lsum0 += __shfl_xor_sync(0xffffffffu, lsum0, 2);
    lsum1 += __shfl_xor_sync(0xffffffffu, lsum1, 1);
    lsum1 += __shfl_xor_sync(0xffffffffu, lsum1, 2);
    float inv0 = 1.f / lsum0, inv1 = 1.f / lsum1;

    int g = lane >> 2, q = lane & 3;
    int trow = 16 * w + g;
    #pragma unroll
    for (int nt = 0; nt < 8; nt++) {
        int c = nt * 8 + 2 * q;
        __half2 lo = __floats2half2_rn(oacc[nt][0] * inv0, oacc[nt][1] * inv0);
        __half2 hi = __floats2half2_rn(oacc[nt][2] * inv1, oacc[nt][3] * inv1);
        Pc[c][trow]         = __low2half(lo);
        Pc[c + 1][trow]     = __high2half(lo);
        Pc[c][trow + 8]     = __low2half(hi);
        Pc[c + 1][trow + 8] = __high2half(hi);
    }
    __syncthreads();

    #pragma unroll
    for (int u = 0; u < 4; u++) {
        int idx = tid + u * 256;
        int c = idx >> 4, pos = idx & 15;
        uint4 v = *(uint4*)&Pc[c][pos * 8];
        *(uint4*)&g_attnh[((size_t)b * C_ + h * DH_ + c) * L_ + t0 + pos * 8] = v;
    }
}

// ---------------------------------------------------------------------------
extern "C" void kernel_launch(void* const* d_in, const int* in_sizes, int n_in,
                              void* d_out, int out_size) {
    const float* x      = (const float*)d_in[0];
    const float* gs     = (const float*)d_in[1];
    const float* gb     = (const float*)d_in[2];
    const float* qkv_w  = (const float*)d_in[3];
    const float* qkv_b  = (const float*)d_in[4];
    const float* proj_w = (const float*)d_in[5];
    const float* proj_b = (const float*)d_in[6];
    float* out = (float*)d_out;

    __half *xnh, *qkvh, *attnh, *wqkvh, *wprojh;
    cudaGetSymbolAddress((void**)&xnh,    g_xnh);
    cudaGetSymbolAddress((void**)&qkvh,   g_qkvh);
    cudaGetSymbolAddress((void**)&attnh,  g_attnh);
    cudaGetSymbolAddress((void**)&wqkvh,  g_wqkvh);
    cudaGetSymbolAddress((void**)&wprojh, g_wprojh);

    cudaFuncSetAttribute(attn_kernel, cudaFuncAttributeMaxDynamicSharedMemorySize,
                         73728);
    cudaFuncSetAttribute(gemm_mma_kernel, cudaFuncAttributeMaxDynamicSharedMemorySize,
                         56832);

    // 1. GroupNorm -> fp16 [b][c][l]  (+ fused weight conversion blocks)
    gn_kernel<<<B_ * NG_ + 64, 256>>>(x, gs, gb, qkv_w, proj_w);

    // 2. qkv GEMM: M=1536, K=512 (q rows scaled by log2e/8 in epilogue)
    {
        dim3 grid(L_ / 128, (3 * C_) / 128, B_);
        gemm_mma_kernel<<<grid, 256, 56832>>>(wqkvh, qkv_b, xnh, nullptr, qkvh,
                                              3 * C_, 0);
    }

    // 3. register-resident flash attention (R10 best)
    {
        dim3 grid(L_ / 128, B_ * NH_);
        attn_kernel<<<grid, 256, 73728>>>();
    }

    // 4. proj GEMM + bias + residual -> fp32 out
    {
        dim3 grid(L_ / 128, C_ / 128, B_);
        gemm_mma_kernel<<<grid, 256, 56832>>>(wprojh, proj_b, attnh, x, out,
                                              C_, 1);
    }
}

// round 13
// speedup vs baseline: 1.1301x; 1.0128x over previous
#include <cuda_runtime.h>
#include <cuda_bf16.h>
#include <cuda_fp16.h>
#include <math.h>
#include <stdint.h>

#define B_ 8
#define C_ 512
#define L_ 1024
#define NH_ 8
#define DH_ 64
#define NG_ 32

// scratch (no cudaMalloc allowed)
__device__ __half g_xnh[B_ * C_ * L_];            // [b][c][l]  8 MB
__device__ __half g_qkvh[B_ * 3 * C_ * L_];       // [b][m][l] 24 MB
__device__ __half g_attnh[B_ * C_ * L_];          // [b][c][l]  8 MB
__device__ __half g_wqkvh[3 * C_ * C_];           // [m][c]
__device__ __half g_wprojh[C_ * C_];              // [m][c]

// ---------------------------------------------------------------------------
// asm helpers
// ---------------------------------------------------------------------------
__device__ __forceinline__ void cp16(void* dst_smem, const void* src) {
    unsigned d = (unsigned)__cvta_generic_to_shared(dst_smem);
    asm volatile("cp.async.cg.shared.global [%0], [%1], 16;\n" :: "r"(d), "l"(src));
}
__device__ __forceinline__ void cp_commit() {
    asm volatile("cp.async.commit_group;\n");
}
template <int N> __device__ __forceinline__ void cp_wait() {
    asm volatile("cp.async.wait_group %0;\n" :: "n"(N));
}
__device__ __forceinline__ void ldsm4(unsigned* r, const void* p) {
    unsigned a = (unsigned)__cvta_generic_to_shared(p);
    asm volatile("ldmatrix.sync.aligned.m8n8.x4.shared.b16 {%0,%1,%2,%3}, [%4];\n"
                 : "=r"(r[0]), "=r"(r[1]), "=r"(r[2]), "=r"(r[3]) : "r"(a));
}
__device__ __forceinline__ void ldsm4t(unsigned* r, const void* p) {
    unsigned a = (unsigned)__cvta_generic_to_shared(p);
    asm volatile("ldmatrix.sync.aligned.m8n8.x4.trans.shared.b16 {%0,%1,%2,%3}, [%4];\n"
                 : "=r"(r[0]), "=r"(r[1]), "=r"(r[2]), "=r"(r[3]) : "r"(a));
}
__device__ __forceinline__ void mma16816(float* d, const unsigned* a,
                                         const unsigned* b, const float* c) {
    asm volatile(
        "mma.sync.aligned.m16n8k16.row.col.f32.f16.f16.f32 "
        "{%0,%1,%2,%3}, {%4,%5,%6,%7}, {%8,%9}, {%10,%11,%12,%13};\n"
        : "=f"(d[0]), "=f"(d[1]), "=f"(d[2]), "=f"(d[3])
        : "r"(a[0]), "r"(a[1]), "r"(a[2]), "r"(a[3]), "r"(b[0]), "r"(b[1]),
          "f"(c[0]), "f"(c[1]), "f"(c[2]), "f"(c[3]));
}
__device__ __forceinline__ unsigned packh2(float a, float b) {
    __half2 h = __floats2half2_rn(a, b);
    return *(unsigned*)&h;
}
__device__ __forceinline__ unsigned ex2h2(unsigned x) {
    unsigned r;
    asm("ex2.approx.f16x2 %0, %1;" : "=r"(r) : "r"(x));
    return r;
}

// ---------------------------------------------------------------------------
// GroupNorm(32) with smem-cached tile (single DRAM read) + fused weight conv.
// Blocks [0,256): GN per (b, group), 512 threads, 64KB dyn smem.
// Blocks [256,320): weight fp32->fp16.
// ---------------------------------------------------------------------------
__global__ __launch_bounds__(512) void gn_kernel(
        const float* __restrict__ x,
        const float* __restrict__ gs,
        const float* __restrict__ gb,
        const float* __restrict__ qkv_w,
        const float* __restrict__ proj_w) {
    extern __shared__ float xs[];    // 16384 floats (64 KB)

    int tid = threadIdx.x;
    if (blockIdx.x >= 256) {
        int blk = blockIdx.x - 256;
        #pragma unroll
        for (int u = 0; u < 8; u++) {
            int i4 = blk * 4096 + tid + u * 512;
            int i = i4 * 4;
            float4 v;
            __half2* dst;
            if (i < 3 * C_ * C_) {
                v = *(const float4*)&qkv_w[i];
                dst = (__half2*)&g_wqkvh[i];
            } else {
                v = *(const float4*)&proj_w[i - 3 * C_ * C_];
                dst = (__half2*)&g_wprojh[i - 3 * C_ * C_];
            }
            dst[0] = __floats2half2_rn(v.x, v.y);
            dst[1] = __floats2half2_rn(v.z, v.w);
        }
        return;
    }

    int b = blockIdx.x >> 5;
    int g = blockIdx.x & 31;
    const float* xp = x + ((size_t)b * C_ + (size_t)g * 16) * L_;
    __half* op = g_xnh + ((size_t)b * C_ + (size_t)g * 16) * L_;

    // single global read: stage to smem while accumulating moments
    float sum = 0.f, sq = 0.f;
    #pragma unroll
    for (int u = 0; u < 8; u++) {
        int i = tid + u * 512;               // float4 index, 4096 total
        float4 v = ((const float4*)xp)[i];
        *(float4*)&xs[i * 4] = v;
        sum += v.x + v.y + v.z + v.w;
        sq  += v.x * v.x + v.y * v.y + v.z * v.z + v.w * v.w;
    }
    __shared__ float ssum[16], ssq[16];
    int lane = tid & 31, wid = tid >> 5;
    #pragma unroll
    for (int m = 16; m > 0; m >>= 1) {
        sum += __shfl_xor_sync(0xffffffffu, sum, m);
        sq  += __shfl_xor_sync(0xffffffffu, sq,  m);
    }
    if (lane == 0) { ssum[wid] = sum; ssq[wid] = sq; }
    __syncthreads();
    if (wid == 0) {
        float s = (lane < 16) ? ssum[lane] : 0.f;
        float q = (lane < 16) ? ssq[lane] : 0.f;
        #pragma unroll
        for (int m = 8; m > 0; m >>= 1) {
            s += __shfl_xor_sync(0xffffffffu, s, m);
            q += __shfl_xor_sync(0xffffffffu, q, m);
        }
        if (lane == 0) { ssum[0] = s; ssq[0] = q; }
    }
    __syncthreads();
    float mu = ssum[0] * (1.f / 16384.f);
    float var = ssq[0] * (1.f / 16384.f) - mu * mu;
    float inv = rsqrtf(var + 1e-5f);

    #pragma unroll
    for (int u = 0; u < 8; u++) {
        int i = tid + u * 512;
        int ch = g * 16 + (i >> 8);
        float sc = gs[ch] * inv;
        float bs = gb[ch] - mu * sc;
        float4 v = *(const float4*)&xs[i * 4];
        __half2 h0 = __floats2half2_rn(v.x * sc + bs, v.y * sc + bs);
        __half2 h1 = __floats2half2_rn(v.z * sc + bs, v.w * sc + bs);
        ((__half2*)op)[2 * i]     = h0;
        ((__half2*)op)[2 * i + 1] = h1;
    }
}

// ---------------------------------------------------------------------------
// Raw-mma fp16 GEMM, 3-stage cp.async ring, ONE barrier per K-iteration.
// Stage indices rotated incrementally (no %3 in the hot loop).
// dyn smem: As 3x128x40 + Bs 3x32x136 halfs = 56832 B
// ---------------------------------------------------------------------------
__global__ __launch_bounds__(256) void gemm_mma_kernel(
        const __half* __restrict__ Wh, const float* __restrict__ bias,
        const __half* __restrict__ X, const float* __restrict__ res,
        void* __restrict__ Y, int M, int mode) {
    extern __shared__ __align__(16) unsigned char gsm[];
    __half (*As)[128][40] = (__half (*)[128][40])gsm;            // 30720 B
    __half (*Bs)[32][136] = (__half (*)[32][136])(gsm + 30720);  // 26112 B

    int tid = threadIdx.x;
    int wid = tid >> 5;
    int lane = tid & 31;
    int wm = wid & 3;
    int wn = wid >> 2;
    int bz = blockIdx.z;
    int m0 = blockIdx.y * 128;
    int n0 = blockIdx.x * 128;
    const __half* Xb = X + (size_t)bz * C_ * L_;

    float acc[2][8][4];
    #pragma unroll
    for (int mt = 0; mt < 2; mt++)
        #pragma unroll
        for (int nt = 0; nt < 8; nt++)
            #pragma unroll
            for (int e = 0; e < 4; e++) acc[mt][nt][e] = 0.f;

    int a_r0 = tid >> 2,          a_c0 = (tid & 3) << 3;
    int a_r1 = (tid + 256) >> 2,  a_c1 = ((tid + 256) & 3) << 3;
    int b_r0 = tid >> 4,          b_c0 = (tid & 15) << 3;
    int b_r1 = (tid + 256) >> 4,  b_c1 = ((tid + 256) & 15) << 3;

    #pragma unroll
    for (int p = 0; p < 2; p++) {
        int k0 = p * 32;
        cp16(&As[p][a_r0][a_c0], &Wh[(size_t)(m0 + a_r0) * C_ + k0 + a_c0]);
        cp16(&As[p][a_r1][a_c1], &Wh[(size_t)(m0 + a_r1) * C_ + k0 + a_c1]);
        cp16(&Bs[p][b_r0][b_c0], &Xb[(size_t)(k0 + b_r0) * L_ + n0 + b_c0]);
        cp16(&Bs[p][b_r1][b_c1], &Xb[(size_t)(k0 + b_r1) * L_ + n0 + b_c1]);
        cp_commit();
    }

    int arow = wm * 32 + (lane & 7) + ((lane >> 3) & 1) * 8;
    int acol = ((lane >> 4) & 1) * 8;
    int brow = (lane & 7) + ((lane >> 3) & 1) * 8;
    int bcol = wn * 64 + ((lane >> 4) & 1) * 8;

    const int NIT = C_ / 32;     // 16
    int s = 0, sp = 2;           // current stage, prefetch stage (rotated)
    for (int it = 0; it < NIT; it++) {
        if (it + 1 < NIT) cp_wait<1>(); else cp_wait<0>();
        __syncthreads();
        if (it + 2 < NIT) {
            int k0 = (it + 2) * 32;
            cp16(&As[sp][a_r0][a_c0], &Wh[(size_t)(m0 + a_r0) * C_ + k0 + a_c0]);
            cp16(&As[sp][a_r1][a_c1], &Wh[(size_t)(m0 + a_r1) * C_ + k0 + a_c1]);
            cp16(&Bs[sp][b_r0][b_c0], &Xb[(size_t)(k0 + b_r0) * L_ + n0 + b_c0]);
            cp16(&Bs[sp][b_r1][b_c1], &Xb[(size_t)(k0 + b_r1) * L_ + n0 + b_c1]);
            cp_commit();
        }

        #pragma unroll
        for (int kk = 0; kk < 32; kk += 16) {
            unsigned af[2][4];
            ldsm4(af[0], &As[s][arow][kk + acol]);
            ldsm4(af[1], &As[s][arow + 16][kk + acol]);
            #pragma unroll
            for (int g = 0; g < 4; g++) {
                unsigned bf[4];
                ldsm4t(bf, &Bs[s][kk + brow][bcol + g * 16]);
                mma16816(acc[0][2 * g],     af[0], bf,     acc[0][2 * g]);
                mma16816(acc[0][2 * g + 1], af[0], bf + 2, acc[0][2 * g + 1]);
                mma16816(acc[1][2 * g],     af[1], bf,     acc[1][2 * g]);
                mma16816(acc[1][2 * g + 1], af[1], bf + 2, acc[1][2 * g + 1]);
            }
        }
        s = (s == 2) ? 0 : s + 1;
        sp = (sp == 2) ? 0 : sp + 1;
    }

    int rbase = m0 + wm * 32 + (lane >> 2);
    int cbase = n0 + wn * 64 + (lane & 3) * 2;

    if (mode == 0) {
        __half* Yh = (__half*)Y + (size_t)bz * M * L_;
        #pragma unroll
        for (int mt = 0; mt < 2; mt++) {
            int r = rbase + mt * 16;
            float bs0 = bias[r], bs1 = bias[r + 8];
            float sc0 = (r < 512)     ? 0.18033688011112043f : 1.f;
            float sc1 = (r + 8 < 512) ? 0.18033688011112043f : 1.f;
            #pragma unroll
            for (int nt = 0; nt < 8; nt++) {
                int c = cbase + nt * 8;
                float* a = acc[mt][nt];
                *(__half2*)&Yh[(size_t)r * L_ + c] =
                    __floats2half2_rn((a[0] + bs0) * sc0, (a[1] + bs0) * sc0);
                *(__half2*)&Yh[(size_t)(r + 8) * L_ + c] =
                    __floats2half2_rn((a[2] + bs1) * sc1, (a[3] + bs1) * sc1);
            }
        }
    } else {
        float* Yf = (float*)Y + (size_t)bz * M * L_;
        const float* Rb = res + (size_t)bz * M * L_;
        #pragma unroll
        for (int mt = 0; mt < 2; mt++) {
            int r = rbase + mt * 16;
            float bs0 = bias[r], bs1 = bias[r + 8];
            #pragma unroll
            for (int nt = 0; nt < 8; nt++) {
                int c = cbase + nt * 8;
                float* a = acc[mt][nt];
                float2 r0 = *(const float2*)&Rb[(size_t)r * L_ + c];
                float2 r1 = *(const float2*)&Rb[(size_t)(r + 8) * L_ + c];
                float2 o0 = make_float2(a[0] + bs0 + r0.x, a[1] + bs0 + r0.y);
                float2 o1 = make_float2(a[2] + bs1 + r1.x, a[3] + bs1 + r1.y);
                *(float2*)&Yf[(size_t)r * L_ + c] = o0;
                *(float2*)&Yf[(size_t)(r + 8) * L_ + c] = o1;
            }
        }
    }
}

// ---------------------------------------------------------------------------
// Register-resident flash attention — R10/R12 version (best measured).
// smem: Qh[128][72] | Kh[3][64][72] | Vh[3][64][72]   (73728 B dynamic)
// ---------------------------------------------------------------------------
__global__ __launch_bounds__(256) void attn_kernel() {
    extern __shared__ __align__(16) unsigned char dsm[];
    __half (*Qh)[72]     = (__half (*)[72])dsm;                  // 18432 B
    __half (*Kh)[64][72] = (__half (*)[64][72])(dsm + 18432);    // 27648 B
    __half (*Vh)[64][72] = (__half (*)[64][72])(dsm + 46080);    // 27648 B
    __half (*Pc)[136]    = (__half (*)[136])(dsm + 18432);       // alias (17408 B)

    int bh = blockIdx.y;
    int b = bh >> 3, h = bh & 7;
    int t0 = blockIdx.x * 128;

    const __half* Qg = g_qkvh + ((size_t)b * 3 * C_ + (size_t)h * DH_) * L_;
    const __half* Kg = Qg + (size_t)C_ * L_;
    const __half* Vg = Qg + (size_t)2 * C_ * L_;

    int tid = threadIdx.x;
    int lane = tid & 31;
    int w = tid >> 5;

    int kr0 = tid >> 3, kc0 = (tid & 7) << 3;
    int kr1 = (tid + 256) >> 3, kc1 = ((tid + 256) & 7) << 3;

    cp16(&Kh[0][kr0][kc0], &Kg[(size_t)kr0 * L_ + kc0]);
    cp16(&Kh[0][kr1][kc1], &Kg[(size_t)kr1 * L_ + kc1]);
    cp16(&Vh[0][kr0][kc0], &Vg[(size_t)kr0 * L_ + kc0]);
    cp16(&Vh[0][kr1][kc1], &Vg[(size_t)kr1 * L_ + kc1]);
    cp_commit();
    cp16(&Kh[1][kr0][kc0], &Kg[(size_t)kr0 * L_ + 64 + kc0]);
    cp16(&Kh[1][kr1][kc1], &Kg[(size_t)kr1 * L_ + 64 + kc1]);
    cp16(&Vh[1][kr0][kc0], &Vg[(size_t)kr0 * L_ + 64 + kc0]);
    cp16(&Vh[1][kr1][kc1], &Vg[(size_t)kr1 * L_ + 64 + kc1]);
    cp_commit();

    #pragma unroll
    for (int u = 0; u < 32; u++) {
        int idx = tid + u * 256;
        int c = idx >> 7, t = idx & 127;
        Qh[t][c] = Qg[(size_t)c * L_ + t0 + t];
    }
    __syncthreads();

    unsigned qa[4][4];
    {
        int m = 16 * w + (lane & 7) + ((lane >> 3) & 1) * 8;
        int cb = ((lane >> 4) & 1) * 8;
        #pragma unroll
        for (int kk = 0; kk < 4; kk++)
            ldsm4(qa[kk], &Qh[m][kk * 16 + cb]);
    }

    float oacc[8][4];
    #pragma unroll
    for (int nt = 0; nt < 8; nt++)
        #pragma unroll
        for (int e = 0; e < 4; e++) oacc[nt][e] = 0.f;
    float lsum0 = 0.f, lsum1 = 0.f;

    int kq_row = ((lane >> 3) & 1) * 8 + (lane & 7);
    int kq_col = ((lane >> 4) & 1) * 8;
    int vq_row = ((lane >> 4) & 1) * 8 + (lane & 7);
    int vq_col = ((lane >> 3) & 1) * 8;

    int s = 0, sp = 2;
    for (int it = 0; it < 16; it++) {
        if (it < 15) cp_wait<1>(); else cp_wait<0>();
        __syncthreads();
        if (it < 14) {
            int s0 = (it + 2) * 64;
            cp16(&Kh[sp][kr0][kc0], &Kg[(size_t)kr0 * L_ + s0 + kc0]);
            cp16(&Kh[sp][kr1][kc1], &Kg[(size_t)kr1 * L_ + s0 + kc1]);
            cp16(&Vh[sp][kr0][kc0], &Vg[(size_t)kr0 * L_ + s0 + kc0]);
            cp16(&Vh[sp][kr1][kc1], &Vg[(size_t)kr1 * L_ + s0 + kc1]);
            cp_commit();
        }

        float sacc[8][4];
        #pragma unroll
        for (int nt = 0; nt < 8; nt++)
            #pragma unroll
            for (int e = 0; e < 4; e++) sacc[nt][e] = 0.f;

        #pragma unroll
        for (int kk = 0; kk < 4; kk++) {
            #pragma unroll
            for (int st = 0; st < 4; st++) {
                unsigned kb[4];
                ldsm4t(kb, &Kh[s][kk * 16 + kq_row][st * 16 + kq_col]);
                mma16816(sacc[2 * st],     qa[kk], kb,     sacc[2 * st]);
                mma16816(sacc[2 * st + 1], qa[kk], kb + 2, sacc[2 * st + 1]);
            }
        }

        unsigned pa[8][2];
        __half2 t0h = __float2half2_rn(0.f), t1h = __float2half2_rn(0.f);
        #pragma unroll
        for (int nt = 0; nt < 8; nt++) {
            pa[nt][0] = ex2h2(packh2(sacc[nt][0], sacc[nt][1]));
            pa[nt][1] = ex2h2(packh2(sacc[nt][2], sacc[nt][3]));
            t0h = __hadd2(t0h, *(__half2*)&pa[nt][0]);
            t1h = __hadd2(t1h, *(__half2*)&pa[nt][1]);
        }
        {
            float2 f0 = __half22float2(t0h);
            float2 f1 = __half22float2(t1h);
            lsum0 += f0.x + f0.y;
            lsum1 += f1.x + f1.y;
        }

        #pragma unroll
        for (int kc = 0; kc < 4; kc++) {
            unsigned af[4] = {pa[2 * kc][0], pa[2 * kc][1],
                              pa[2 * kc + 1][0], pa[2 * kc + 1][1]};
            #pragma unroll
            for (int ct = 0; ct < 4; ct++) {
                unsigned vb[4];
                ldsm4(vb, &Vh[s][ct * 16 + vq_row][kc * 16 + vq_col]);
                mma16816(oacc[2 * ct],     af, vb,     oacc[2 * ct]);
                mma16816(oacc[2 * ct + 1], af, vb + 2, oacc[2 * ct + 1]);
            }
        }
        s = (s == 2) ? 0 : s + 1;
        sp = (sp == 2) ? 0 : sp + 1;
    }
    __syncthreads();

    lsum0 += __shfl_xor_sync(0xffffffffu, lsum0, 1);
    lsum0 += __shfl_xor_sync(0xffffffffu, lsum0, 2);
    lsum1 += __shfl_xor_sync(0xffffffffu, lsum1, 1);
    lsum1 += __shfl_xor_sync(0xffffffffu, lsum1, 2);
    float inv0 = 1.f / lsum0, inv1 = 1.f / lsum1;

    int g = lane >> 2, q = lane & 3;
    int trow = 16 * w + g;
    #pragma unroll
    for (int nt = 0; nt < 8; nt++) {
        int c = nt * 8 + 2 * q;
        __half2 lo = __floats2half2_rn(oacc[nt][0] * inv0, oacc[nt][1] * inv0);
        __half2 hi = __floats2half2_rn(oacc[nt][2] * inv1, oacc[nt][3] * inv1);
        Pc[c][trow]         = __low2half(lo);
        Pc[c + 1][trow]     = __high2half(lo);
        Pc[c][trow + 8]     = __low2half(hi);
        Pc[c + 1][trow + 8] = __high2half(hi);
    }
    __syncthreads();

    #pragma unroll
    for (int u = 0; u < 4; u++) {
        int idx = tid + u * 256;
        int c = idx >> 4, pos = idx & 15;
        uint4 v = *(uint4*)&Pc[c][pos * 8];
        *(uint4*)&g_attnh[((size_t)b * C_ + h * DH_ + c) * L_ + t0 + pos * 8] = v;
    }
}

// ---------------------------------------------------------------------------
extern "C" void kernel_launch(void* const* d_in, const int* in_sizes, int n_in,
                              void* d_out, int out_size) {
    const float* x      = (const float*)d_in[0];
    const float* gs     = (const float*)d_in[1];
    const float* gb     = (const float*)d_in[2];
    const float* qkv_w  = (const float*)d_in[3];
    const float* qkv_b  = (const float*)d_in[4];
    const float* proj_w = (const float*)d_in[5];
    const float* proj_b = (const float*)d_in[6];
    float* out = (float*)d_out;

    __half *xnh, *qkvh, *attnh, *wqkvh, *wprojh;
    cudaGetSymbolAddress((void**)&xnh,    g_xnh);
    cudaGetSymbolAddress((void**)&qkvh,   g_qkvh);
    cudaGetSymbolAddress((void**)&attnh,  g_attnh);
    cudaGetSymbolAddress((void**)&wqkvh,  g_wqkvh);
    cudaGetSymbolAddress((void**)&wprojh, g_wprojh);

    cudaFuncSetAttribute(attn_kernel, cudaFuncAttributeMaxDynamicSharedMemorySize,
                         73728);
    cudaFuncSetAttribute(gemm_mma_kernel, cudaFuncAttributeMaxDynamicSharedMemorySize,
                         56832);
    cudaFuncSetAttribute(gn_kernel, cudaFuncAttributeMaxDynamicSharedMemorySize,
                         65536);

    // 1. GroupNorm (smem-cached, 512 thr) -> fp16 [b][c][l]  (+ weight conv)
    gn_kernel<<<B_ * NG_ + 64, 512, 65536>>>(x, gs, gb, qkv_w, proj_w);

    // 2. qkv GEMM: M=1536, K=512 (q rows scaled by log2e/8 in epilogue)
    {
        dim3 grid(L_ / 128, (3 * C_) / 128, B_);
        gemm_mma_kernel<<<grid, 256, 56832>>>(wqkvh, qkv_b, xnh, nullptr, qkvh,
                                              3 * C_, 0);
    }

    // 3. register-resident flash attention
    {
        dim3 grid(L_ / 128, B_ * NH_);
        attn_kernel<<<grid, 256, 73728>>>();
    }

    // 4. proj GEMM + bias + residual -> fp32 out
    {
        dim3 grid(L_ / 128, C_ / 128, B_);
        gemm_mma_kernel<<<grid, 256, 56832>>>(wprojh, proj_b, attnh, x, out,
                                              C_, 1);
    }
}

// round 14
// speedup vs baseline: 1.1487x; 1.0165x over previous
#include <cuda_runtime.h>
#include <cuda_bf16.h>
#include <cuda_fp16.h>
#include <math.h>
#include <stdint.h>

#define B_ 8
#define C_ 512
#define L_ 1024
#define NH_ 8
#define DH_ 64
#define NG_ 32

// scratch (no cudaMalloc allowed)
__device__ __half g_xnh[B_ * C_ * L_];            // [b][c][l]  8 MB
__device__ __half g_qkvh[B_ * 3 * C_ * L_];       // [b][m][l] 24 MB
__device__ __half g_attnh[B_ * C_ * L_];          // [b][c][l]  8 MB
__device__ __half g_wqkvh[3 * C_ * C_];           // [m][c]
__device__ __half g_wprojh[C_ * C_];              // [m][c]

// ---------------------------------------------------------------------------
// asm helpers
// ---------------------------------------------------------------------------
__device__ __forceinline__ void cp16(void* dst_smem, const void* src) {
    unsigned d = (unsigned)__cvta_generic_to_shared(dst_smem);
    asm volatile("cp.async.cg.shared.global [%0], [%1], 16;\n" :: "r"(d), "l"(src));
}
__device__ __forceinline__ void cp_commit() {
    asm volatile("cp.async.commit_group;\n");
}
template <int N> __device__ __forceinline__ void cp_wait() {
    asm volatile("cp.async.wait_group %0;\n" :: "n"(N));
}
__device__ __forceinline__ void ldsm4(unsigned* r, const void* p) {
    unsigned a = (unsigned)__cvta_generic_to_shared(p);
    asm volatile("ldmatrix.sync.aligned.m8n8.x4.shared.b16 {%0,%1,%2,%3}, [%4];\n"
                 : "=r"(r[0]), "=r"(r[1]), "=r"(r[2]), "=r"(r[3]) : "r"(a));
}
__device__ __forceinline__ void ldsm4t(unsigned* r, const void* p) {
    unsigned a = (unsigned)__cvta_generic_to_shared(p);
    asm volatile("ldmatrix.sync.aligned.m8n8.x4.trans.shared.b16 {%0,%1,%2,%3}, [%4];\n"
                 : "=r"(r[0]), "=r"(r[1]), "=r"(r[2]), "=r"(r[3]) : "r"(a));
}
__device__ __forceinline__ void mma16816(float* d, const unsigned* a,
                                         const unsigned* b, const float* c) {
    asm volatile(
        "mma.sync.aligned.m16n8k16.row.col.f32.f16.f16.f32 "
        "{%0,%1,%2,%3}, {%4,%5,%6,%7}, {%8,%9}, {%10,%11,%12,%13};\n"
        : "=f"(d[0]), "=f"(d[1]), "=f"(d[2]), "=f"(d[3])
        : "r"(a[0]), "r"(a[1]), "r"(a[2]), "r"(a[3]), "r"(b[0]), "r"(b[1]),
          "f"(c[0]), "f"(c[1]), "f"(c[2]), "f"(c[3]));
}
__device__ __forceinline__ unsigned packh2(float a, float b) {
    __half2 h = __floats2half2_rn(a, b);
    return *(unsigned*)&h;
}
__device__ __forceinline__ unsigned ex2h2(unsigned x) {
    unsigned r;
    asm("ex2.approx.f16x2 %0, %1;" : "=r"(r) : "r"(x));
    return r;
}

// ---------------------------------------------------------------------------
// GroupNorm(32) with smem-cached tile + fused weight conversion (R13, passing)
// ---------------------------------------------------------------------------
__global__ __launch_bounds__(512) void gn_kernel(
        const float* __restrict__ x,
        const float* __restrict__ gs,
        const float* __restrict__ gb,
        const float* __restrict__ qkv_w,
        const float* __restrict__ proj_w) {
    extern __shared__ float xs[];    // 16384 floats (64 KB)

    int tid = threadIdx.x;
    if (blockIdx.x >= 256) {
        int blk = blockIdx.x - 256;
        #pragma unroll
        for (int u = 0; u < 8; u++) {
            int i4 = blk * 4096 + tid + u * 512;
            int i = i4 * 4;
            float4 v;
            __half2* dst;
            if (i < 3 * C_ * C_) {
                v = *(const float4*)&qkv_w[i];
                dst = (__half2*)&g_wqkvh[i];
            } else {
                v = *(const float4*)&proj_w[i - 3 * C_ * C_];
                dst = (__half2*)&g_wprojh[i - 3 * C_ * C_];
            }
            dst[0] = __floats2half2_rn(v.x, v.y);
            dst[1] = __floats2half2_rn(v.z, v.w);
        }
        return;
    }

    int b = blockIdx.x >> 5;
    int g = blockIdx.x & 31;
    const float* xp = x + ((size_t)b * C_ + (size_t)g * 16) * L_;
    __half* op = g_xnh + ((size_t)b * C_ + (size_t)g * 16) * L_;

    float sum = 0.f, sq = 0.f;
    #pragma unroll
    for (int u = 0; u < 8; u++) {
        int i = tid + u * 512;
        float4 v = ((const float4*)xp)[i];
        *(float4*)&xs[i * 4] = v;
        sum += v.x + v.y + v.z + v.w;
        sq  += v.x * v.x + v.y * v.y + v.z * v.z + v.w * v.w;
    }
    __shared__ float ssum[16], ssq[16];
    int lane = tid & 31, wid = tid >> 5;
    #pragma unroll
    for (int m = 16; m > 0; m >>= 1) {
        sum += __shfl_xor_sync(0xffffffffu, sum, m);
        sq  += __shfl_xor_sync(0xffffffffu, sq,  m);
    }
    if (lane == 0) { ssum[wid] = sum; ssq[wid] = sq; }
    __syncthreads();
    if (wid == 0) {
        float s = (lane < 16) ? ssum[lane] : 0.f;
        float q = (lane < 16) ? ssq[lane] : 0.f;
        #pragma unroll
        for (int m = 8; m > 0; m >>= 1) {
            s += __shfl_xor_sync(0xffffffffu, s, m);
            q += __shfl_xor_sync(0xffffffffu, q, m);
        }
        if (lane == 0) { ssum[0] = s; ssq[0] = q; }
    }
    __syncthreads();
    float mu = ssum[0] * (1.f / 16384.f);
    float var = ssq[0] * (1.f / 16384.f) - mu * mu;
    float inv = rsqrtf(var + 1e-5f);

    #pragma unroll
    for (int u = 0; u < 8; u++) {
        int i = tid + u * 512;
        int ch = g * 16 + (i >> 8);
        float sc = gs[ch] * inv;
        float bs = gb[ch] - mu * sc;
        float4 v = *(const float4*)&xs[i * 4];
        __half2 h0 = __floats2half2_rn(v.x * sc + bs, v.y * sc + bs);
        __half2 h1 = __floats2half2_rn(v.z * sc + bs, v.w * sc + bs);
        ((__half2*)op)[2 * i]     = h0;
        ((__half2*)op)[2 * i + 1] = h1;
    }
}

// ---------------------------------------------------------------------------
// Raw-mma fp16 GEMM, 5-stage cp.async ring (prefetch distance 4), one
// barrier per K-iteration. dyn smem: 5 x (As 128x40 + Bs 32x136) = 94720 B
// ---------------------------------------------------------------------------
__global__ __launch_bounds__(256) void gemm_mma_kernel(
        const __half* __restrict__ Wh, const float* __restrict__ bias,
        const __half* __restrict__ X, const float* __restrict__ res,
        void* __restrict__ Y, int M, int mode) {
    extern __shared__ __align__(16) unsigned char gsm[];
    __half (*As)[128][40] = (__half (*)[128][40])gsm;            // 51200 B
    __half (*Bs)[32][136] = (__half (*)[32][136])(gsm + 51200);  // 43520 B

    int tid = threadIdx.x;
    int wid = tid >> 5;
    int lane = tid & 31;
    int wm = wid & 3;
    int wn = wid >> 2;
    int bz = blockIdx.z;
    int m0 = blockIdx.y * 128;
    int n0 = blockIdx.x * 128;
    const __half* Xb = X + (size_t)bz * C_ * L_;

    float acc[2][8][4];
    #pragma unroll
    for (int mt = 0; mt < 2; mt++)
        #pragma unroll
        for (int nt = 0; nt < 8; nt++)
            #pragma unroll
            for (int e = 0; e < 4; e++) acc[mt][nt][e] = 0.f;

    int a_r0 = tid >> 2,          a_c0 = (tid & 3) << 3;
    int a_r1 = (tid + 256) >> 2,  a_c1 = ((tid + 256) & 3) << 3;
    int b_r0 = tid >> 4,          b_c0 = (tid & 15) << 3;
    int b_r1 = (tid + 256) >> 4,  b_c1 = ((tid + 256) & 15) << 3;

    // prologue: stages 0..3
    #pragma unroll
    for (int p = 0; p < 4; p++) {
        int k0 = p * 32;
        cp16(&As[p][a_r0][a_c0], &Wh[(size_t)(m0 + a_r0) * C_ + k0 + a_c0]);
        cp16(&As[p][a_r1][a_c1], &Wh[(size_t)(m0 + a_r1) * C_ + k0 + a_c1]);
        cp16(&Bs[p][b_r0][b_c0], &Xb[(size_t)(k0 + b_r0) * L_ + n0 + b_c0]);
        cp16(&Bs[p][b_r1][b_c1], &Xb[(size_t)(k0 + b_r1) * L_ + n0 + b_c1]);
        cp_commit();
    }

    int arow = wm * 32 + (lane & 7) + ((lane >> 3) & 1) * 8;
    int acol = ((lane >> 4) & 1) * 8;
    int brow = (lane & 7) + ((lane >> 3) & 1) * 8;
    int bcol = wn * 64 + ((lane >> 4) & 1) * 8;

    const int NIT = C_ / 32;     // 16
    int s = 0, sp = 4;           // current stage, prefetch stage (rotated mod 5)
    for (int it = 0; it < NIT; it++) {
        if (it + 3 < NIT) cp_wait<3>();
        else if (it + 2 < NIT) cp_wait<2>();
        else if (it + 1 < NIT) cp_wait<1>();
        else cp_wait<0>();
        __syncthreads();
        if (it + 4 < NIT) {
            int k0 = (it + 4) * 32;
            cp16(&As[sp][a_r0][a_c0], &Wh[(size_t)(m0 + a_r0) * C_ + k0 + a_c0]);
            cp16(&As[sp][a_r1][a_c1], &Wh[(size_t)(m0 + a_r1) * C_ + k0 + a_c1]);
            cp16(&Bs[sp][b_r0][b_c0], &Xb[(size_t)(k0 + b_r0) * L_ + n0 + b_c0]);
            cp16(&Bs[sp][b_r1][b_c1], &Xb[(size_t)(k0 + b_r1) * L_ + n0 + b_c1]);
            cp_commit();
        }

        #pragma unroll
        for (int kk = 0; kk < 32; kk += 16) {
            unsigned af[2][4];
            ldsm4(af[0], &As[s][arow][kk + acol]);
            ldsm4(af[1], &As[s][arow + 16][kk + acol]);
            #pragma unroll
            for (int g = 0; g < 4; g++) {
                unsigned bf[4];
                ldsm4t(bf, &Bs[s][kk + brow][bcol + g * 16]);
                mma16816(acc[0][2 * g],     af[0], bf,     acc[0][2 * g]);
                mma16816(acc[0][2 * g + 1], af[0], bf + 2, acc[0][2 * g + 1]);
                mma16816(acc[1][2 * g],     af[1], bf,     acc[1][2 * g]);
                mma16816(acc[1][2 * g + 1], af[1], bf + 2, acc[1][2 * g + 1]);
            }
        }
        s = (s == 4) ? 0 : s + 1;
        sp = (sp == 4) ? 0 : sp + 1;
    }

    int rbase = m0 + wm * 32 + (lane >> 2);
    int cbase = n0 + wn * 64 + (lane & 3) * 2;

    if (mode == 0) {
        __half* Yh = (__half*)Y + (size_t)bz * M * L_;
        #pragma unroll
        for (int mt = 0; mt < 2; mt++) {
            int r = rbase + mt * 16;
            float bs0 = bias[r], bs1 = bias[r + 8];
            float sc0 = (r < 512)     ? 0.18033688011112043f : 1.f;
            float sc1 = (r + 8 < 512) ? 0.18033688011112043f : 1.f;
            #pragma unroll
            for (int nt = 0; nt < 8; nt++) {
                int c = cbase + nt * 8;
                float* a = acc[mt][nt];
                *(__half2*)&Yh[(size_t)r * L_ + c] =
                    __floats2half2_rn((a[0] + bs0) * sc0, (a[1] + bs0) * sc0);
                *(__half2*)&Yh[(size_t)(r + 8) * L_ + c] =
                    __floats2half2_rn((a[2] + bs1) * sc1, (a[3] + bs1) * sc1);
            }
        }
    } else {
        float* Yf = (float*)Y + (size_t)bz * M * L_;
        const float* Rb = res + (size_t)bz * M * L_;
        #pragma unroll
        for (int mt = 0; mt < 2; mt++) {
            int r = rbase + mt * 16;
            float bs0 = bias[r], bs1 = bias[r + 8];
            #pragma unroll
            for (int nt = 0; nt < 8; nt++) {
                int c = cbase + nt * 8;
                float* a = acc[mt][nt];
                float2 r0 = *(const float2*)&Rb[(size_t)r * L_ + c];
                float2 r1 = *(const float2*)&Rb[(size_t)(r + 8) * L_ + c];
                float2 o0 = make_float2(a[0] + bs0 + r0.x, a[1] + bs0 + r0.y);
                float2 o1 = make_float2(a[2] + bs1 + r1.x, a[3] + bs1 + r1.y);
                *(float2*)&Yf[(size_t)r * L_ + c] = o0;
                *(float2*)&Yf[(size_t)(r + 8) * L_ + c] = o1;
            }
        }
    }
}

// ---------------------------------------------------------------------------
// Register-resident flash attention — R10/R12/R13 version (best measured).
// smem: Qh[128][72] | Kh[3][64][72] | Vh[3][64][72]   (73728 B dynamic)
// ---------------------------------------------------------------------------
__global__ __launch_bounds__(256) void attn_kernel() {
    extern __shared__ __align__(16) unsigned char dsm[];
    __half (*Qh)[72]     = (__half (*)[72])dsm;                  // 18432 B
    __half (*Kh)[64][72] = (__half (*)[64][72])(dsm + 18432);    // 27648 B
    __half (*Vh)[64][72] = (__half (*)[64][72])(dsm + 46080);    // 27648 B
    __half (*Pc)[136]    = (__half (*)[136])(dsm + 18432);       // alias (17408 B)

    int bh = blockIdx.y;
    int b = bh >> 3, h = bh & 7;
    int t0 = blockIdx.x * 128;

    const __half* Qg = g_qkvh + ((size_t)b * 3 * C_ + (size_t)h * DH_) * L_;
    const __half* Kg = Qg + (size_t)C_ * L_;
    const __half* Vg = Qg + (size_t)2 * C_ * L_;

    int tid = threadIdx.x;
    int lane = tid & 31;
    int w = tid >> 5;

    int kr0 = tid >> 3, kc0 = (tid & 7) << 3;
    int kr1 = (tid + 256) >> 3, kc1 = ((tid + 256) & 7) << 3;

    cp16(&Kh[0][kr0][kc0], &Kg[(size_t)kr0 * L_ + kc0]);
    cp16(&Kh[0][kr1][kc1], &Kg[(size_t)kr1 * L_ + kc1]);
    cp16(&Vh[0][kr0][kc0], &Vg[(size_t)kr0 * L_ + kc0]);
    cp16(&Vh[0][kr1][kc1], &Vg[(size_t)kr1 * L_ + kc1]);
    cp_commit();
    cp16(&Kh[1][kr0][kc0], &Kg[(size_t)kr0 * L_ + 64 + kc0]);
    cp16(&Kh[1][kr1][kc1], &Kg[(size_t)kr1 * L_ + 64 + kc1]);
    cp16(&Vh[1][kr0][kc0], &Vg[(size_t)kr0 * L_ + 64 + kc0]);
    cp16(&Vh[1][kr1][kc1], &Vg[(size_t)kr1 * L_ + 64 + kc1]);
    cp_commit();

    #pragma unroll
    for (int u = 0; u < 32; u++) {
        int idx = tid + u * 256;
        int c = idx >> 7, t = idx & 127;
        Qh[t][c] = Qg[(size_t)c * L_ + t0 + t];
    }
    __syncthreads();

    unsigned qa[4][4];
    {
        int m = 16 * w + (lane & 7) + ((lane >> 3) & 1) * 8;
        int cb = ((lane >> 4) & 1) * 8;
        #pragma unroll
        for (int kk = 0; kk < 4; kk++)
            ldsm4(qa[kk], &Qh[m][kk * 16 + cb]);
    }

    float oacc[8][4];
    #pragma unroll
    for (int nt = 0; nt < 8; nt++)
        #pragma unroll
        for (int e = 0; e < 4; e++) oacc[nt][e] = 0.f;
    float lsum0 = 0.f, lsum1 = 0.f;

    int kq_row = ((lane >> 3) & 1) * 8 + (lane & 7);
    int kq_col = ((lane >> 4) & 1) * 8;
    int vq_row = ((lane >> 4) & 1) * 8 + (lane & 7);
    int vq_col = ((lane >> 3) & 1) * 8;

    int s = 0, sp = 2;
    for (int it = 0; it < 16; it++) {
        if (it < 15) cp_wait<1>(); else cp_wait<0>();
        __syncthreads();
        if (it < 14) {
            int s0 = (it + 2) * 64;
            cp16(&Kh[sp][kr0][kc0], &Kg[(size_t)kr0 * L_ + s0 + kc0]);
            cp16(&Kh[sp][kr1][kc1], &Kg[(size_t)kr1 * L_ + s0 + kc1]);
            cp16(&Vh[sp][kr0][kc0], &Vg[(size_t)kr0 * L_ + s0 + kc0]);
            cp16(&Vh[sp][kr1][kc1], &Vg[(size_t)kr1 * L_ + s0 + kc1]);
            cp_commit();
        }

        float sacc[8][4];
        #pragma unroll
        for (int nt = 0; nt < 8; nt++)
            #pragma unroll
            for (int e = 0; e < 4; e++) sacc[nt][e] = 0.f;

        #pragma unroll
        for (int kk = 0; kk < 4; kk++) {
            #pragma unroll
            for (int st = 0; st < 4; st++) {
                unsigned kb[4];
                ldsm4t(kb, &Kh[s][kk * 16 + kq_row][st * 16 + kq_col]);
                mma16816(sacc[2 * st],     qa[kk], kb,     sacc[2 * st]);
                mma16816(sacc[2 * st + 1], qa[kk], kb + 2, sacc[2 * st + 1]);
            }
        }

        unsigned pa[8][2];
        __half2 t0h = __float2half2_rn(0.f), t1h = __float2half2_rn(0.f);
        #pragma unroll
        for (int nt = 0; nt < 8; nt++) {
            pa[nt][0] = ex2h2(packh2(sacc[nt][0], sacc[nt][1]));
            pa[nt][1] = ex2h2(packh2(sacc[nt][2], sacc[nt][3]));
            t0h = __hadd2(t0h, *(__half2*)&pa[nt][0]);
            t1h = __hadd2(t1h, *(__half2*)&pa[nt][1]);
        }
        {
            float2 f0 = __half22float2(t0h);
            float2 f1 = __half22float2(t1h);
            lsum0 += f0.x + f0.y;
            lsum1 += f1.x + f1.y;
        }

        #pragma unroll
        for (int kc = 0; kc < 4; kc++) {
            unsigned af[4] = {pa[2 * kc][0], pa[2 * kc][1],
                              pa[2 * kc + 1][0], pa[2 * kc + 1][1]};
            #pragma unroll
            for (int ct = 0; ct < 4; ct++) {
                unsigned vb[4];
                ldsm4(vb, &Vh[s][ct * 16 + vq_row][kc * 16 + vq_col]);
                mma16816(oacc[2 * ct],     af, vb,     oacc[2 * ct]);
                mma16816(oacc[2 * ct + 1], af, vb + 2, oacc[2 * ct + 1]);
            }
        }
        s = (s == 2) ? 0 : s + 1;
        sp = (sp == 2) ? 0 : sp + 1;
    }
    __syncthreads();

    lsum0 += __shfl_xor_sync(0xffffffffu, lsum0, 1);
    lsum0 += __shfl_xor_sync(0xffffffffu, lsum0, 2);
    lsum1 += __shfl_xor_sync(0xffffffffu, lsum1, 1);
    lsum1 += __shfl_xor_sync(0xffffffffu, lsum1, 2);
    float inv0 = 1.f / lsum0, inv1 = 1.f / lsum1;

    int g = lane >> 2, q = lane & 3;
    int trow = 16 * w + g;
    #pragma unroll
    for (int nt = 0; nt < 8; nt++) {
        int c = nt * 8 + 2 * q;
        __half2 lo = __floats2half2_rn(oacc[nt][0] * inv0, oacc[nt][1] * inv0);
        __half2 hi = __floats2half2_rn(oacc[nt][2] * inv1, oacc[nt][3] * inv1);
        Pc[c][trow]         = __low2half(lo);
        Pc[c + 1][trow]     = __high2half(lo);
        Pc[c][trow + 8]     = __low2half(hi);
        Pc[c + 1][trow + 8] = __high2half(hi);
    }
    __syncthreads();

    #pragma unroll
    for (int u = 0; u < 4; u++) {
        int idx = tid + u * 256;
        int c = idx >> 4, pos = idx & 15;
        uint4 v = *(uint4*)&Pc[c][pos * 8];
        *(uint4*)&g_attnh[((size_t)b * C_ + h * DH_ + c) * L_ + t0 + pos * 8] = v;
    }
}

// ---------------------------------------------------------------------------
extern "C" void kernel_launch(void* const* d_in, const int* in_sizes, int n_in,
                              void* d_out, int out_size) {
    const float* x      = (const float*)d_in[0];
    const float* gs     = (const float*)d_in[1];
    const float* gb     = (const float*)d_in[2];
    const float* qkv_w  = (const float*)d_in[3];
    const float* qkv_b  = (const float*)d_in[4];
    const float* proj_w = (const float*)d_in[5];
    const float* proj_b = (const float*)d_in[6];
    float* out = (float*)d_out;

    __half *xnh, *qkvh, *attnh, *wqkvh, *wprojh;
    cudaGetSymbolAddress((void**)&xnh,    g_xnh);
    cudaGetSymbolAddress((void**)&qkvh,   g_qkvh);
    cudaGetSymbolAddress((void**)&attnh,  g_attnh);
    cudaGetSymbolAddress((void**)&wqkvh,  g_wqkvh);
    cudaGetSymbolAddress((void**)&wprojh, g_wprojh);

    cudaFuncSetAttribute(attn_kernel, cudaFuncAttributeMaxDynamicSharedMemorySize,
                         73728);
    cudaFuncSetAttribute(gemm_mma_kernel, cudaFuncAttributeMaxDynamicSharedMemorySize,
                         94720);
    cudaFuncSetAttribute(gn_kernel, cudaFuncAttributeMaxDynamicSharedMemorySize,
                         65536);

    // 1. GroupNorm (smem-cached) -> fp16 [b][c][l]  (+ weight conv)
    gn_kernel<<<B_ * NG_ + 64, 512, 65536>>>(x, gs, gb, qkv_w, proj_w);

    // 2. qkv GEMM: M=1536, K=512 (q rows scaled by log2e/8 in epilogue)
    {
        dim3 grid(L_ / 128, (3 * C_) / 128, B_);
        gemm_mma_kernel<<<grid, 256, 94720>>>(wqkvh, qkv_b, xnh, nullptr, qkvh,
                                              3 * C_, 0);
    }

    // 3. register-resident flash attention
    {
        dim3 grid(L_ / 128, B_ * NH_);
        attn_kernel<<<grid, 256, 73728>>>();
    }

    // 4. proj GEMM + bias + residual -> fp32 out
    {
        dim3 grid(L_ / 128, C_ / 128, B_);
        gemm_mma_kernel<<<grid, 256, 94720>>>(wprojh, proj_b, attnh, x, out,
                                              C_, 1);
    }
}

// round 15
// speedup vs baseline: 1.2416x; 1.0809x over previous
#include <cuda_runtime.h>
#include <cuda_bf16.h>
#include <cuda_fp16.h>
#include <math.h>
#include <stdint.h>

#define B_ 8
#define C_ 512
#define L_ 1024
#define NH_ 8
#define DH_ 64
#define NG_ 32

// scratch (no cudaMalloc allowed)
__device__ __half g_xnh[B_ * C_ * L_];            // [b][c][l]  8 MB
__device__ __half g_qkvh[B_ * 3 * C_ * L_];       // [b][m][l] 24 MB
__device__ __half g_attnh[B_ * C_ * L_];          // [b][c][l]  8 MB
__device__ __half g_wqkvh[3 * C_ * C_];           // [m][c]
__device__ __half g_wprojh[C_ * C_];              // [m][c]

// ---------------------------------------------------------------------------
// asm helpers
// ---------------------------------------------------------------------------
__device__ __forceinline__ void cp16(void* dst_smem, const void* src) {
    unsigned d = (unsigned)__cvta_generic_to_shared(dst_smem);
    asm volatile("cp.async.cg.shared.global [%0], [%1], 16;\n" :: "r"(d), "l"(src));
}
__device__ __forceinline__ void cp_commit() {
    asm volatile("cp.async.commit_group;\n");
}
template <int N> __device__ __forceinline__ void cp_wait() {
    asm volatile("cp.async.wait_group %0;\n" :: "n"(N));
}
__device__ __forceinline__ void ldsm4(unsigned* r, const void* p) {
    unsigned a = (unsigned)__cvta_generic_to_shared(p);
    asm volatile("ldmatrix.sync.aligned.m8n8.x4.shared.b16 {%0,%1,%2,%3}, [%4];\n"
                 : "=r"(r[0]), "=r"(r[1]), "=r"(r[2]), "=r"(r[3]) : "r"(a));
}
__device__ __forceinline__ void ldsm4t(unsigned* r, const void* p) {
    unsigned a = (unsigned)__cvta_generic_to_shared(p);
    asm volatile("ldmatrix.sync.aligned.m8n8.x4.trans.shared.b16 {%0,%1,%2,%3}, [%4];\n"
                 : "=r"(r[0]), "=r"(r[1]), "=r"(r[2]), "=r"(r[3]) : "r"(a));
}
__device__ __forceinline__ void mma16816(float* d, const unsigned* a,
                                         const unsigned* b, const float* c) {
    asm volatile(
        "mma.sync.aligned.m16n8k16.row.col.f32.f16.f16.f32 "
        "{%0,%1,%2,%3}, {%4,%5,%6,%7}, {%8,%9}, {%10,%11,%12,%13};\n"
        : "=f"(d[0]), "=f"(d[1]), "=f"(d[2]), "=f"(d[3])
        : "r"(a[0]), "r"(a[1]), "r"(a[2]), "r"(a[3]), "r"(b[0]), "r"(b[1]),
          "f"(c[0]), "f"(c[1]), "f"(c[2]), "f"(c[3]));
}
// fp16-accumulator variant: D/C are 2 b32 regs (4 halves)
__device__ __forceinline__ void mma16816h(unsigned* d, const unsigned* a,
                                          const unsigned* b, const unsigned* c) {
    asm volatile(
        "mma.sync.aligned.m16n8k16.row.col.f16.f16.f16.f16 "
        "{%0,%1}, {%2,%3,%4,%5}, {%6,%7}, {%8,%9};\n"
        : "=r"(d[0]), "=r"(d[1])
        : "r"(a[0]), "r"(a[1]), "r"(a[2]), "r"(a[3]), "r"(b[0]), "r"(b[1]),
          "r"(c[0]), "r"(c[1]));
}
__device__ __forceinline__ unsigned ex2h2(unsigned x) {
    unsigned r;
    asm("ex2.approx.f16x2 %0, %1;" : "=r"(r) : "r"(x));
    return r;
}

// ---------------------------------------------------------------------------
// GroupNorm(32) with smem-cached tile + fused weight conversion (R13, passing)
// ---------------------------------------------------------------------------
__global__ __launch_bounds__(512) void gn_kernel(
        const float* __restrict__ x,
        const float* __restrict__ gs,
        const float* __restrict__ gb,
        const float* __restrict__ qkv_w,
        const float* __restrict__ proj_w) {
    extern __shared__ float xs[];    // 16384 floats (64 KB)

    int tid = threadIdx.x;
    if (blockIdx.x >= 256) {
        int blk = blockIdx.x - 256;
        #pragma unroll
        for (int u = 0; u < 8; u++) {
            int i4 = blk * 4096 + tid + u * 512;
            int i = i4 * 4;
            float4 v;
            __half2* dst;
            if (i < 3 * C_ * C_) {
                v = *(const float4*)&qkv_w[i];
                dst = (__half2*)&g_wqkvh[i];
            } else {
                v = *(const float4*)&proj_w[i - 3 * C_ * C_];
                dst = (__half2*)&g_wprojh[i - 3 * C_ * C_];
            }
            dst[0] = __floats2half2_rn(v.x, v.y);
            dst[1] = __floats2half2_rn(v.z, v.w);
        }
        return;
    }

    int b = blockIdx.x >> 5;
    int g = blockIdx.x & 31;
    const float* xp = x + ((size_t)b * C_ + (size_t)g * 16) * L_;
    __half* op = g_xnh + ((size_t)b * C_ + (size_t)g * 16) * L_;

    float sum = 0.f, sq = 0.f;
    #pragma unroll
    for (int u = 0; u < 8; u++) {
        int i = tid + u * 512;
        float4 v = ((const float4*)xp)[i];
        *(float4*)&xs[i * 4] = v;
        sum += v.x + v.y + v.z + v.w;
        sq  += v.x * v.x + v.y * v.y + v.z * v.z + v.w * v.w;
    }
    __shared__ float ssum[16], ssq[16];
    int lane = tid & 31, wid = tid >> 5;
    #pragma unroll
    for (int m = 16; m > 0; m >>= 1) {
        sum += __shfl_xor_sync(0xffffffffu, sum, m);
        sq  += __shfl_xor_sync(0xffffffffu, sq,  m);
    }
    if (lane == 0) { ssum[wid] = sum; ssq[wid] = sq; }
    __syncthreads();
    if (wid == 0) {
        float s = (lane < 16) ? ssum[lane] : 0.f;
        float q = (lane < 16) ? ssq[lane] : 0.f;
        #pragma unroll
        for (int m = 8; m > 0; m >>= 1) {
            s += __shfl_xor_sync(0xffffffffu, s, m);
            q += __shfl_xor_sync(0xffffffffu, q, m);
        }
        if (lane == 0) { ssum[0] = s; ssq[0] = q; }
    }
    __syncthreads();
    float mu = ssum[0] * (1.f / 16384.f);
    float var = ssq[0] * (1.f / 16384.f) - mu * mu;
    float inv = rsqrtf(var + 1e-5f);

    #pragma unroll
    for (int u = 0; u < 8; u++) {
        int i = tid + u * 512;
        int ch = g * 16 + (i >> 8);
        float sc = gs[ch] * inv;
        float bs = gb[ch] - mu * sc;
        float4 v = *(const float4*)&xs[i * 4];
        __half2 h0 = __floats2half2_rn(v.x * sc + bs, v.y * sc + bs);
        __half2 h1 = __floats2half2_rn(v.z * sc + bs, v.w * sc + bs);
        ((__half2*)op)[2 * i]     = h0;
        ((__half2*)op)[2 * i + 1] = h1;
    }
}

// ---------------------------------------------------------------------------
// Raw-mma fp16 GEMM: 128 threads, block tile 64m x 128n, 4 warps (2m x 2n),
// warp tile 32x64, BK=32, 3-stage cp.async ring, 1 barrier/iter.
// 4 blocks/SM (independent barrier domains hide each other's waits).
// dyn smem: 3 x (As 64x40 + Bs 32x136) halfs = 41472 B
// ---------------------------------------------------------------------------
__global__ __launch_bounds__(128, 4) void gemm_mma_kernel(
        const __half* __restrict__ Wh, const float* __restrict__ bias,
        const __half* __restrict__ X, const float* __restrict__ res,
        void* __restrict__ Y, int M, int mode) {
    extern __shared__ __align__(16) unsigned char gsm[];
    __half (*As)[64][40]  = (__half (*)[64][40])gsm;             // 15360 B
    __half (*Bs)[32][136] = (__half (*)[32][136])(gsm + 15360);  // 26112 B

    int tid = threadIdx.x;
    int wid = tid >> 5;
    int lane = tid & 31;
    int wm = wid & 1;
    int wn = wid >> 1;
    int bz = blockIdx.z;
    int m0 = blockIdx.y * 64;
    int n0 = blockIdx.x * 128;
    const __half* Xb = X + (size_t)bz * C_ * L_;

    float acc[2][8][4];
    #pragma unroll
    for (int mt = 0; mt < 2; mt++)
        #pragma unroll
        for (int nt = 0; nt < 8; nt++)
            #pragma unroll
            for (int e = 0; e < 4; e++) acc[mt][nt][e] = 0.f;

    // A: 64x32 halfs = 256 chunks (4/row); B: 32x128 halfs = 512 chunks (16/row)
    int a_r0 = tid >> 2,          a_c0 = (tid & 3) << 3;
    int a_r1 = (tid + 128) >> 2,  a_c1 = ((tid + 128) & 3) << 3;
    int b_r0 = tid >> 4,          b_c0 = (tid & 15) << 3;
    int b_r1 = (tid + 128) >> 4,  b_c1 = ((tid + 128) & 15) << 3;
    int b_r2 = (tid + 256) >> 4,  b_c2 = ((tid + 256) & 15) << 3;
    int b_r3 = (tid + 384) >> 4,  b_c3 = ((tid + 384) & 15) << 3;

    // prologue: stages 0,1
    #pragma unroll
    for (int p = 0; p < 2; p++) {
        int k0 = p * 32;
        cp16(&As[p][a_r0][a_c0], &Wh[(size_t)(m0 + a_r0) * C_ + k0 + a_c0]);
        cp16(&As[p][a_r1][a_c1], &Wh[(size_t)(m0 + a_r1) * C_ + k0 + a_c1]);
        cp16(&Bs[p][b_r0][b_c0], &Xb[(size_t)(k0 + b_r0) * L_ + n0 + b_c0]);
        cp16(&Bs[p][b_r1][b_c1], &Xb[(size_t)(k0 + b_r1) * L_ + n0 + b_c1]);
        cp16(&Bs[p][b_r2][b_c2], &Xb[(size_t)(k0 + b_r2) * L_ + n0 + b_c2]);
        cp16(&Bs[p][b_r3][b_c3], &Xb[(size_t)(k0 + b_r3) * L_ + n0 + b_c3]);
        cp_commit();
    }

    int arow = wm * 32 + (lane & 7) + ((lane >> 3) & 1) * 8;
    int acol = ((lane >> 4) & 1) * 8;
    int brow = (lane & 7) + ((lane >> 3) & 1) * 8;
    int bcol = wn * 64 + ((lane >> 4) & 1) * 8;

    const int NIT = C_ / 32;     // 16
    int s = 0, sp = 2;
    for (int it = 0; it < NIT; it++) {
        if (it + 1 < NIT) cp_wait<1>(); else cp_wait<0>();
        __syncthreads();
        if (it + 2 < NIT) {
            int k0 = (it + 2) * 32;
            cp16(&As[sp][a_r0][a_c0], &Wh[(size_t)(m0 + a_r0) * C_ + k0 + a_c0]);
            cp16(&As[sp][a_r1][a_c1], &Wh[(size_t)(m0 + a_r1) * C_ + k0 + a_c1]);
            cp16(&Bs[sp][b_r0][b_c0], &Xb[(size_t)(k0 + b_r0) * L_ + n0 + b_c0]);
            cp16(&Bs[sp][b_r1][b_c1], &Xb[(size_t)(k0 + b_r1) * L_ + n0 + b_c1]);
            cp16(&Bs[sp][b_r2][b_c2], &Xb[(size_t)(k0 + b_r2) * L_ + n0 + b_c2]);
            cp16(&Bs[sp][b_r3][b_c3], &Xb[(size_t)(k0 + b_r3) * L_ + n0 + b_c3]);
            cp_commit();
        }

        #pragma unroll
        for (int kk = 0; kk < 32; kk += 16) {
            unsigned af[2][4];
            ldsm4(af[0], &As[s][arow][kk + acol]);
            ldsm4(af[1], &As[s][arow + 16][kk + acol]);
            #pragma unroll
            for (int g = 0; g < 4; g++) {
                unsigned bf[4];
                ldsm4t(bf, &Bs[s][kk + brow][bcol + g * 16]);
                mma16816(acc[0][2 * g],     af[0], bf,     acc[0][2 * g]);
                mma16816(acc[0][2 * g + 1], af[0], bf + 2, acc[0][2 * g + 1]);
                mma16816(acc[1][2 * g],     af[1], bf,     acc[1][2 * g]);
                mma16816(acc[1][2 * g + 1], af[1], bf + 2, acc[1][2 * g + 1]);
            }
        }
        s = (s == 2) ? 0 : s + 1;
        sp = (sp == 2) ? 0 : sp + 1;
    }

    int rbase = m0 + wm * 32 + (lane >> 2);
    int cbase = n0 + wn * 64 + (lane & 3) * 2;

    if (mode == 0) {
        __half* Yh = (__half*)Y + (size_t)bz * M * L_;
        #pragma unroll
        for (int mt = 0; mt < 2; mt++) {
            int r = rbase + mt * 16;
            float bs0 = bias[r], bs1 = bias[r + 8];
            float sc0 = (r < 512)     ? 0.18033688011112043f : 1.f;
            float sc1 = (r + 8 < 512) ? 0.18033688011112043f : 1.f;
            #pragma unroll
            for (int nt = 0; nt < 8; nt++) {
                int c = cbase + nt * 8;
                float* a = acc[mt][nt];
                *(__half2*)&Yh[(size_t)r * L_ + c] =
                    __floats2half2_rn((a[0] + bs0) * sc0, (a[1] + bs0) * sc0);
                *(__half2*)&Yh[(size_t)(r + 8) * L_ + c] =
                    __floats2half2_rn((a[2] + bs1) * sc1, (a[3] + bs1) * sc1);
            }
        }
    } else {
        float* Yf = (float*)Y + (size_t)bz * M * L_;
        const float* Rb = res + (size_t)bz * M * L_;
        #pragma unroll
        for (int mt = 0; mt < 2; mt++) {
            int r = rbase + mt * 16;
            float bs0 = bias[r], bs1 = bias[r + 8];
            #pragma unroll
            for (int nt = 0; nt < 8; nt++) {
                int c = cbase + nt * 8;
                float* a = acc[mt][nt];
                float2 r0 = *(const float2*)&Rb[(size_t)r * L_ + c];
                float2 r1 = *(const float2*)&Rb[(size_t)(r + 8) * L_ + c];
                float2 o0 = make_float2(a[0] + bs0 + r0.x, a[1] + bs0 + r0.y);
                float2 o1 = make_float2(a[2] + bs1 + r1.x, a[3] + bs1 + r1.y);
                *(float2*)&Yf[(size_t)r * L_ + c] = o0;
                *(float2*)&Yf[(size_t)(r + 8) * L_ + c] = o1;
            }
        }
    }
}

// ---------------------------------------------------------------------------
// Register-resident flash attention; S=QK^T now uses fp16 accumulators whose
// D-register layout equals the pa fragments directly (no packh2 conversions).
// smem: Qh[128][72] | Kh[3][64][72] | Vh[3][64][72]   (73728 B dynamic)
// ---------------------------------------------------------------------------
__global__ __launch_bounds__(256) void attn_kernel() {
    extern __shared__ __align__(16) unsigned char dsm[];
    __half (*Qh)[72]     = (__half (*)[72])dsm;                  // 18432 B
    __half (*Kh)[64][72] = (__half (*)[64][72])(dsm + 18432);    // 27648 B
    __half (*Vh)[64][72] = (__half (*)[64][72])(dsm + 46080);    // 27648 B
    __half (*Pc)[136]    = (__half (*)[136])(dsm + 18432);       // alias (17408 B)

    int bh = blockIdx.y;
    int b = bh >> 3, h = bh & 7;
    int t0 = blockIdx.x * 128;

    const __half* Qg = g_qkvh + ((size_t)b * 3 * C_ + (size_t)h * DH_) * L_;
    const __half* Kg = Qg + (size_t)C_ * L_;
    const __half* Vg = Qg + (size_t)2 * C_ * L_;

    int tid = threadIdx.x;
    int lane = tid & 31;
    int w = tid >> 5;

    int kr0 = tid >> 3, kc0 = (tid & 7) << 3;
    int kr1 = (tid + 256) >> 3, kc1 = ((tid + 256) & 7) << 3;

    cp16(&Kh[0][kr0][kc0], &Kg[(size_t)kr0 * L_ + kc0]);
    cp16(&Kh[0][kr1][kc1], &Kg[(size_t)kr1 * L_ + kc1]);
    cp16(&Vh[0][kr0][kc0], &Vg[(size_t)kr0 * L_ + kc0]);
    cp16(&Vh[0][kr1][kc1], &Vg[(size_t)kr1 * L_ + kc1]);
    cp_commit();
    cp16(&Kh[1][kr0][kc0], &Kg[(size_t)kr0 * L_ + 64 + kc0]);
    cp16(&Kh[1][kr1][kc1], &Kg[(size_t)kr1 * L_ + 64 + kc1]);
    cp16(&Vh[1][kr0][kc0], &Vg[(size_t)kr0 * L_ + 64 + kc0]);
    cp16(&Vh[1][kr1][kc1], &Vg[(size_t)kr1 * L_ + 64 + kc1]);
    cp_commit();

    #pragma unroll
    for (int u = 0; u < 32; u++) {
        int idx = tid + u * 256;
        int c = idx >> 7, t = idx & 127;
        Qh[t][c] = Qg[(size_t)c * L_ + t0 + t];
    }
    __syncthreads();

    unsigned qa[4][4];
    {
        int m = 16 * w + (lane & 7) + ((lane >> 3) & 1) * 8;
        int cb = ((lane >> 4) & 1) * 8;
        #pragma unroll
        for (int kk = 0; kk < 4; kk++)
            ldsm4(qa[kk], &Qh[m][kk * 16 + cb]);
    }

    float oacc[8][4];
    #pragma unroll
    for (int nt = 0; nt < 8; nt++)
        #pragma unroll
        for (int e = 0; e < 4; e++) oacc[nt][e] = 0.f;
    float lsum0 = 0.f, lsum1 = 0.f;

    int kq_row = ((lane >> 3) & 1) * 8 + (lane & 7);
    int kq_col = ((lane >> 4) & 1) * 8;
    int vq_row = ((lane >> 4) & 1) * 8 + (lane & 7);
    int vq_col = ((lane >> 3) & 1) * 8;

    int s = 0, sp = 2;
    for (int it = 0; it < 16; it++) {
        if (it < 15) cp_wait<1>(); else cp_wait<0>();
        __syncthreads();
        if (it < 14) {
            int s0 = (it + 2) * 64;
            cp16(&Kh[sp][kr0][kc0], &Kg[(size_t)kr0 * L_ + s0 + kc0]);
            cp16(&Kh[sp][kr1][kc1], &Kg[(size_t)kr1 * L_ + s0 + kc1]);
            cp16(&Vh[sp][kr0][kc0], &Vg[(size_t)kr0 * L_ + s0 + kc0]);
            cp16(&Vh[sp][kr1][kc1], &Vg[(size_t)kr1 * L_ + s0 + kc1]);
            cp_commit();
        }

        // S = Q K with fp16 accumulators (log2-domain; scale folded into q)
        unsigned sd[8][2];
        #pragma unroll
        for (int nt = 0; nt < 8; nt++) { sd[nt][0] = 0u; sd[nt][1] = 0u; }

        #pragma unroll
        for (int kk = 0; kk < 4; kk++) {
            #pragma unroll
            for (int st = 0; st < 4; st++) {
                unsigned kb[4];
                ldsm4t(kb, &Kh[s][kk * 16 + kq_row][st * 16 + kq_col]);
                mma16816h(sd[2 * st],     qa[kk], kb,     sd[2 * st]);
                mma16816h(sd[2 * st + 1], qa[kk], kb + 2, sd[2 * st + 1]);
            }
        }

        // P = exp2(S) directly on half2 accumulators; row sums via HADD2
        unsigned pa[8][2];
        __half2 t0h = __float2half2_rn(0.f), t1h = __float2half2_rn(0.f);
        #pragma unroll
        for (int nt = 0; nt < 8; nt++) {
            pa[nt][0] = ex2h2(sd[nt][0]);
            pa[nt][1] = ex2h2(sd[nt][1]);
            t0h = __hadd2(t0h, *(__half2*)&pa[nt][0]);
            t1h = __hadd2(t1h, *(__half2*)&pa[nt][1]);
        }
        {
            float2 f0 = __half22float2(t0h);
            float2 f1 = __half22float2(t1h);
            lsum0 += f0.x + f0.y;
            lsum1 += f1.x + f1.y;
        }

        // O += P V^T (fp32 accumulators)
        #pragma unroll
        for (int kc = 0; kc < 4; kc++) {
            unsigned af[4] = {pa[2 * kc][0], pa[2 * kc][1],
                              pa[2 * kc + 1][0], pa[2 * kc + 1][1]};
            #pragma unroll
            for (int ct = 0; ct < 4; ct++) {
                unsigned vb[4];
                ldsm4(vb, &Vh[s][ct * 16 + vq_row][kc * 16 + vq_col]);
                mma16816(oacc[2 * ct],     af, vb,     oacc[2 * ct]);
                mma16816(oacc[2 * ct + 1], af, vb + 2, oacc[2 * ct + 1]);
            }
        }
        s = (s == 2) ? 0 : s + 1;
        sp = (sp == 2) ? 0 : sp + 1;
    }
    __syncthreads();

    lsum0 += __shfl_xor_sync(0xffffffffu, lsum0, 1);
    lsum0 += __shfl_xor_sync(0xffffffffu, lsum0, 2);
    lsum1 += __shfl_xor_sync(0xffffffffu, lsum1, 1);
    lsum1 += __shfl_xor_sync(0xffffffffu, lsum1, 2);
    float inv0 = 1.f / lsum0, inv1 = 1.f / lsum1;

    int g = lane >> 2, q = lane & 3;
    int trow = 16 * w + g;
    #pragma unroll
    for (int nt = 0; nt < 8; nt++) {
        int c = nt * 8 + 2 * q;
        __half2 lo = __floats2half2_rn(oacc[nt][0] * inv0, oacc[nt][1] * inv0);
        __half2 hi = __floats2half2_rn(oacc[nt][2] * inv1, oacc[nt][3] * inv1);
        Pc[c][trow]         = __low2half(lo);
        Pc[c + 1][trow]     = __high2half(lo);
        Pc[c][trow + 8]     = __low2half(hi);
        Pc[c + 1][trow + 8] = __high2half(hi);
    }
    __syncthreads();

    #pragma unroll
    for (int u = 0; u < 4; u++) {
        int idx = tid + u * 256;
        int c = idx >> 4, pos = idx & 15;
        uint4 v = *(uint4*)&Pc[c][pos * 8];
        *(uint4*)&g_attnh[((size_t)b * C_ + h * DH_ + c) * L_ + t0 + pos * 8] = v;
    }
}

// ---------------------------------------------------------------------------
extern "C" void kernel_launch(void* const* d_in, const int* in_sizes, int n_in,
                              void* d_out, int out_size) {
    const float* x      = (const float*)d_in[0];
    const float* gs     = (const float*)d_in[1];
    const float* gb     = (const float*)d_in[2];
    const float* qkv_w  = (const float*)d_in[3];
    const float* qkv_b  = (const float*)d_in[4];
    const float* proj_w = (const float*)d_in[5];
    const float* proj_b = (const float*)d_in[6];
    float* out = (float*)d_out;

    __half *xnh, *qkvh, *attnh, *wqkvh, *wprojh;
    cudaGetSymbolAddress((void**)&xnh,    g_xnh);
    cudaGetSymbolAddress((void**)&qkvh,   g_qkvh);
    cudaGetSymbolAddress((void**)&attnh,  g_attnh);
    cudaGetSymbolAddress((void**)&wqkvh,  g_wqkvh);
    cudaGetSymbolAddress((void**)&wprojh, g_wprojh);

    cudaFuncSetAttribute(attn_kernel, cudaFuncAttributeMaxDynamicSharedMemorySize,
                         73728);
    cudaFuncSetAttribute(gemm_mma_kernel, cudaFuncAttributeMaxDynamicSharedMemorySize,
                         41472);
    cudaFuncSetAttribute(gn_kernel, cudaFuncAttributeMaxDynamicSharedMemorySize,
                         65536);

    // 1. GroupNorm (smem-cached) -> fp16 [b][c][l]  (+ weight conv)
    gn_kernel<<<B_ * NG_ + 64, 512, 65536>>>(x, gs, gb, qkv_w, proj_w);

    // 2. qkv GEMM: M=1536, K=512 (q rows scaled by log2e/8 in epilogue)
    {
        dim3 grid(L_ / 128, (3 * C_) / 64, B_);
        gemm_mma_kernel<<<grid, 128, 41472>>>(wqkvh, qkv_b, xnh, nullptr, qkvh,
                                              3 * C_, 0);
    }

    // 3. register-resident flash attention (fp16-acc QK)
    {
        dim3 grid(L_ / 128, B_ * NH_);
        attn_kernel<<<grid, 256, 73728>>>();
    }

    // 4. proj GEMM + bias + residual -> fp32 out
    {
        dim3 grid(L_ / 128, C_ / 64, B_);
        gemm_mma_kernel<<<grid, 128, 41472>>>(wprojh, proj_b, attnh, x, out,
                                              C_, 1);
    }
}